// round 2
// baseline (speedup 1.0000x reference)
#include <cuda_runtime.h>
#include <math.h>

// ---------------------------------------------------------------------------
// AttentionBlock: GroupNorm -> QKV (1x1 conv) -> attention -> proj -> residual
// B=2, C=512, H=W=64 (N=4096 pixels), 32 groups, eps=1e-6
// ---------------------------------------------------------------------------

static constexpr int BSZ  = 2;
static constexpr int CH   = 512;
static constexpr int NPIX = 4096;          // 64*64
static constexpr int NGRP = 32;
static constexpr int CPG  = CH / NGRP;     // 16

// Scratch (static device arrays; no allocation allowed in kernel_launch)
__device__ float g_hn[(size_t)BSZ * CH * NPIX];
__device__ float g_q [(size_t)BSZ * CH * NPIX];
__device__ float g_k [(size_t)BSZ * CH * NPIX];
__device__ float g_v [(size_t)BSZ * CH * NPIX];
__device__ float g_o [(size_t)BSZ * CH * NPIX];
__device__ float g_attn[(size_t)BSZ * NPIX * NPIX];   // 134 MB

// ---------------------------------------------------------------------------
// GroupNorm: one block per (b, g). Group data is contiguous: 16*4096 floats.
// ---------------------------------------------------------------------------
__global__ void groupnorm_kernel(const float* __restrict__ x,
                                 const float* __restrict__ scale,
                                 const float* __restrict__ bias,
                                 float* __restrict__ out)
{
    const int NPG = CPG * NPIX;   // 65536
    const int g   = blockIdx.x & (NGRP - 1);
    const float* xp = x   + (size_t)blockIdx.x * NPG;
    float*       op = out + (size_t)blockIdx.x * NPG;

    float s = 0.f, ss = 0.f;
    for (int i = threadIdx.x; i < NPG; i += blockDim.x) {
        float v = xp[i];
        s  += v;
        ss += v * v;
    }
    __shared__ float sh[64];
    #pragma unroll
    for (int o = 16; o; o >>= 1) {
        s  += __shfl_xor_sync(0xffffffffu, s,  o);
        ss += __shfl_xor_sync(0xffffffffu, ss, o);
    }
    int wid = threadIdx.x >> 5, lid = threadIdx.x & 31;
    if (lid == 0) { sh[wid] = s; sh[32 + wid] = ss; }
    __syncthreads();
    if (threadIdx.x < 32) {
        s  = (lid < 8) ? sh[lid]      : 0.f;
        ss = (lid < 8) ? sh[32 + lid] : 0.f;
        #pragma unroll
        for (int o = 4; o; o >>= 1) {
            s  += __shfl_xor_sync(0xffffffffu, s,  o);
            ss += __shfl_xor_sync(0xffffffffu, ss, o);
        }
        if (lid == 0) { sh[0] = s; sh[1] = ss; }
    }
    __syncthreads();
    float mean = sh[0] / (float)NPG;
    float var  = sh[1] / (float)NPG - mean * mean;
    float rstd = rsqrtf(var + 1e-6f);

    int cbase = g * CPG;
    for (int i = threadIdx.x; i < NPG; i += blockDim.x) {
        int c = cbase + (i >> 12);   // i / 4096
        op[i] = (xp[i] - mean) * rstd * scale[c] + bias[c];
    }
}

// ---------------------------------------------------------------------------
// Tiled SGEMM: C[m,n] = alpha * sum_k A(m,k)*B(k,n)  (+ bias[m]) (+ res[m,n])
//   TA: A stored K x M row-major (A[k*lda + m]); else M x K (A[m*lda + k])
//   TB: B stored N x K row-major (B[n*ldb + k]); else K x N (B[k*ldb + n])
// BM=BN=128, BK=8, 8x8 per thread, 256 threads. All dims divide evenly here.
// ---------------------------------------------------------------------------
template <bool TA, bool TB, bool BIAS, bool RES>
__global__ void __launch_bounds__(256)
sgemm_kernel(int M, int N, int K,
             const float* __restrict__ A, int lda, size_t sA,
             const float* __restrict__ B, int ldb, size_t sB,
             float* __restrict__ Cp, int ldc, size_t sC,
             const float* __restrict__ bias,
             const float* __restrict__ res, size_t sR,
             float alpha)
{
    constexpr int BM = 128, BN = 128, BK = 8, TM = 8, TN = 8;
    __shared__ float As[BK][BM + 4];
    __shared__ float Bs[BK][BN + 4];

    const int bz = blockIdx.z;
    A  += sA * bz;
    B  += sB * bz;
    Cp += sC * bz;
    if (RES) res += sR * bz;

    const int m0 = blockIdx.y * BM;
    const int n0 = blockIdx.x * BN;
    const int tid = threadIdx.x;
    const int tx = tid & 15;   // col group
    const int ty = tid >> 4;   // row group

    float acc[TM][TN];
    #pragma unroll
    for (int i = 0; i < TM; i++)
        #pragma unroll
        for (int j = 0; j < TN; j++)
            acc[i][j] = 0.f;

    for (int k0 = 0; k0 < K; k0 += BK) {
        // ---- load A tile into As[k][m] ----
        #pragma unroll
        for (int t = 0; t < 4; t++) {
            int idx = t * 256 + tid;
            if (TA) {
                int kk = idx >> 7, mm = idx & 127;
                As[kk][mm] = A[(size_t)(k0 + kk) * lda + (m0 + mm)];
            } else {
                int mm = idx >> 3, kk = idx & 7;
                As[kk][mm] = A[(size_t)(m0 + mm) * lda + (k0 + kk)];
            }
        }
        // ---- load B tile into Bs[k][n] ----
        #pragma unroll
        for (int t = 0; t < 4; t++) {
            int idx = t * 256 + tid;
            if (!TB) {
                int kk = idx >> 7, nn = idx & 127;
                Bs[kk][nn] = B[(size_t)(k0 + kk) * ldb + (n0 + nn)];
            } else {
                int nn = idx >> 3, kk = idx & 7;
                Bs[kk][nn] = B[(size_t)(n0 + nn) * ldb + (k0 + kk)];
            }
        }
        __syncthreads();

        #pragma unroll
        for (int kk = 0; kk < BK; kk++) {
            float ar[TM], br[TN];
            #pragma unroll
            for (int i = 0; i < TM; i++) ar[i] = As[kk][ty * TM + i];
            #pragma unroll
            for (int j = 0; j < TN; j++) br[j] = Bs[kk][tx * TN + j];
            #pragma unroll
            for (int i = 0; i < TM; i++)
                #pragma unroll
                for (int j = 0; j < TN; j++)
                    acc[i][j] += ar[i] * br[j];
        }
        __syncthreads();
    }

    // ---- epilogue ----
    #pragma unroll
    for (int i = 0; i < TM; i++) {
        int m = m0 + ty * TM + i;
        float bv = BIAS ? bias[m] : 0.f;
        #pragma unroll
        for (int j = 0; j < TN; j++) {
            int n = n0 + tx * TN + j;
            float v = acc[i][j] * alpha + bv;
            if (RES) v += res[(size_t)m * ldc + n];
            Cp[(size_t)m * ldc + n] = v;
        }
    }
}

// ---------------------------------------------------------------------------
// Row softmax: one block per row of 4096.
// ---------------------------------------------------------------------------
__global__ void __launch_bounds__(256)
softmax_kernel(float* __restrict__ attn)
{
    float* p = attn + (size_t)blockIdx.x * NPIX;
    const int tid = threadIdx.x;
    float lv[16];
    float mx = -1e30f;
    #pragma unroll
    for (int j = 0; j < 16; j++) {
        lv[j] = p[j * 256 + tid];
        mx = fmaxf(mx, lv[j]);
    }

    __shared__ float sh[8];
    #pragma unroll
    for (int o = 16; o; o >>= 1) mx = fmaxf(mx, __shfl_xor_sync(0xffffffffu, mx, o));
    if ((tid & 31) == 0) sh[tid >> 5] = mx;
    __syncthreads();
    if (tid < 32) {
        float v = (tid < 8) ? sh[tid] : -1e30f;
        #pragma unroll
        for (int o = 4; o; o >>= 1) v = fmaxf(v, __shfl_xor_sync(0xffffffffu, v, o));
        if (tid == 0) sh[0] = v;
    }
    __syncthreads();
    mx = sh[0];
    __syncthreads();   // done reading sh before sum-reduction reuses it

    float s = 0.f;
    #pragma unroll
    for (int j = 0; j < 16; j++) {
        lv[j] = __expf(lv[j] - mx);
        s += lv[j];
    }
    #pragma unroll
    for (int o = 16; o; o >>= 1) s += __shfl_xor_sync(0xffffffffu, s, o);
    if ((tid & 31) == 0) sh[tid >> 5] = s;
    __syncthreads();
    if (tid < 32) {
        float v = (tid < 8) ? sh[tid] : 0.f;
        #pragma unroll
        for (int o = 4; o; o >>= 1) v += __shfl_xor_sync(0xffffffffu, v, o);
        if (tid == 0) sh[0] = v;
    }
    __syncthreads();
    float inv = 1.f / sh[0];

    #pragma unroll
    for (int j = 0; j < 16; j++) p[j * 256 + tid] = lv[j] * inv;
}

// ---------------------------------------------------------------------------
// Launch
// ---------------------------------------------------------------------------
extern "C" void kernel_launch(void* const* d_in, const int* in_sizes, int n_in,
                              void* d_out, int out_size)
{
    const float* x        = (const float*)d_in[0];
    const float* gn_scale = (const float*)d_in[1];
    const float* gn_bias  = (const float*)d_in[2];
    const float* wq       = (const float*)d_in[3];
    const float* bq       = (const float*)d_in[4];
    const float* wk       = (const float*)d_in[5];
    const float* bk       = (const float*)d_in[6];
    const float* wv       = (const float*)d_in[7];
    const float* bv       = (const float*)d_in[8];
    const float* wp       = (const float*)d_in[9];
    const float* bp       = (const float*)d_in[10];
    float* out            = (float*)d_out;

    static float *hn = nullptr, *q, *k, *v, *attn, *o;
    if (!hn) {
        cudaGetSymbolAddress((void**)&hn,   g_hn);
        cudaGetSymbolAddress((void**)&q,    g_q);
        cudaGetSymbolAddress((void**)&k,    g_k);
        cudaGetSymbolAddress((void**)&v,    g_v);
        cudaGetSymbolAddress((void**)&attn, g_attn);
        cudaGetSymbolAddress((void**)&o,    g_o);
    }

    const size_t sCN = (size_t)CH * NPIX;      // per-batch stride for [C,N]
    const size_t sNN = (size_t)NPIX * NPIX;    // per-batch stride for [N,N]
    const float inv_sqrt_c = 0.044194173824159216f;  // 1/sqrt(512)

    // 1) GroupNorm
    groupnorm_kernel<<<BSZ * NGRP, 256>>>(x, gn_scale, gn_bias, hn);

    // 2) Q/K/V = W @ hn + b   (M=512, N=4096, K=512, NN)
    dim3 gQKV(NPIX / 128, CH / 128, BSZ);
    sgemm_kernel<false, false, true, false><<<gQKV, 256>>>(
        CH, NPIX, CH, wq, CH, 0, hn, NPIX, sCN, q, NPIX, sCN, bq, nullptr, 0, 1.f);
    sgemm_kernel<false, false, true, false><<<gQKV, 256>>>(
        CH, NPIX, CH, wk, CH, 0, hn, NPIX, sCN, k, NPIX, sCN, bk, nullptr, 0, 1.f);
    sgemm_kernel<false, false, true, false><<<gQKV, 256>>>(
        CH, NPIX, CH, wv, CH, 0, hn, NPIX, sCN, v, NPIX, sCN, bv, nullptr, 0, 1.f);

    // 3) attn[i,j] = (1/sqrt(C)) * sum_c q[c,i]*k[c,j]   (M=N=4096, K=512, TN)
    dim3 gAtt(NPIX / 128, NPIX / 128, BSZ);
    sgemm_kernel<true, false, false, false><<<gAtt, 256>>>(
        NPIX, NPIX, CH, q, NPIX, sCN, k, NPIX, sCN, attn, NPIX, sNN,
        nullptr, nullptr, 0, inv_sqrt_c);

    // 4) row softmax
    softmax_kernel<<<BSZ * NPIX, 256>>>(attn);

    // 5) o[c,i] = sum_j v[c,j]*attn[i,j]   (M=512, N=4096, K=4096, NT)
    sgemm_kernel<false, true, false, false><<<gQKV, 256>>>(
        CH, NPIX, NPIX, v, NPIX, sCN, attn, NPIX, sNN, o, NPIX, sCN,
        nullptr, nullptr, 0, 1.f);

    // 6) out = x + Wp @ o + bp   (M=512, N=4096, K=512, NN + bias + residual)
    sgemm_kernel<false, false, true, true><<<gQKV, 256>>>(
        CH, NPIX, CH, wp, CH, 0, o, NPIX, sCN, out, NPIX, sCN, bp, x, sCN, 1.f);
}

// round 3
// speedup vs baseline: 2.9116x; 2.9116x over previous
#include <cuda_runtime.h>
#include <math.h>
#include <stdint.h>

// ---------------------------------------------------------------------------
// AttentionBlock: GroupNorm -> QKV (1x1 conv) -> attention -> proj -> residual
// B=2, C=512, H=W=64 (N=4096), 32 groups, eps=1e-6
// Round 3: all GEMMs on tf32 tensor cores (mma.sync m16n8k8) with cp.async
// double buffering. GroupNorm / softmax stay fp32.
// ---------------------------------------------------------------------------

static constexpr int BSZ  = 2;
static constexpr int CH   = 512;
static constexpr int NPIX = 4096;
static constexpr int NGRP = 32;
static constexpr int CPG  = CH / NGRP;

__device__ float g_hn[(size_t)BSZ * CH * NPIX];
__device__ float g_q [(size_t)BSZ * CH * NPIX];
__device__ float g_k [(size_t)BSZ * CH * NPIX];
__device__ float g_v [(size_t)BSZ * CH * NPIX];
__device__ float g_o [(size_t)BSZ * CH * NPIX];
__device__ float g_attn[(size_t)BSZ * NPIX * NPIX];

// ---------------------------------------------------------------------------
// GroupNorm
// ---------------------------------------------------------------------------
__global__ void groupnorm_kernel(const float* __restrict__ x,
                                 const float* __restrict__ scale,
                                 const float* __restrict__ bias,
                                 float* __restrict__ out)
{
    const int NPG = CPG * NPIX;
    const int g   = blockIdx.x & (NGRP - 1);
    const float* xp = x   + (size_t)blockIdx.x * NPG;
    float*       op = out + (size_t)blockIdx.x * NPG;

    float s = 0.f, ss = 0.f;
    for (int i = threadIdx.x; i < NPG; i += blockDim.x) {
        float v = xp[i];
        s += v; ss += v * v;
    }
    __shared__ float sh[64];
    #pragma unroll
    for (int o = 16; o; o >>= 1) {
        s  += __shfl_xor_sync(0xffffffffu, s,  o);
        ss += __shfl_xor_sync(0xffffffffu, ss, o);
    }
    int wid = threadIdx.x >> 5, lid = threadIdx.x & 31;
    if (lid == 0) { sh[wid] = s; sh[32 + wid] = ss; }
    __syncthreads();
    if (threadIdx.x < 32) {
        s  = (lid < 8) ? sh[lid]      : 0.f;
        ss = (lid < 8) ? sh[32 + lid] : 0.f;
        #pragma unroll
        for (int o = 4; o; o >>= 1) {
            s  += __shfl_xor_sync(0xffffffffu, s,  o);
            ss += __shfl_xor_sync(0xffffffffu, ss, o);
        }
        if (lid == 0) { sh[0] = s; sh[1] = ss; }
    }
    __syncthreads();
    float mean = sh[0] / (float)NPG;
    float var  = sh[1] / (float)NPG - mean * mean;
    float rstd = rsqrtf(var + 1e-6f);

    int cbase = g * CPG;
    for (int i = threadIdx.x; i < NPG; i += blockDim.x) {
        int c = cbase + (i >> 12);
        op[i] = (xp[i] - mean) * rstd * scale[c] + bias[c];
    }
}

// ---------------------------------------------------------------------------
// tf32 tensor-core GEMM
//   C[m,n] = alpha * sum_k A(m,k)*B(k,n)  (+ bias[m]) (+ res[m,n])
//   TA: A stored K x M row-major; else M x K
//   TB: B stored N x K row-major; else K x N
// BM=BN=128, BK=16, 256 threads (8 warps, 4x2), warp tile 32x64,
// mma.sync.m16n8k8.tf32, cp.async double buffer.
// ---------------------------------------------------------------------------
__device__ __forceinline__ uint32_t f2tf(float x) {
    uint32_t r;
    asm("cvt.rna.tf32.f32 %0, %1;" : "=r"(r) : "f"(x));
    return r;
}
__device__ __forceinline__ void cp16(void* dst, const void* src) {
    uint32_t d = (uint32_t)__cvta_generic_to_shared(dst);
    asm volatile("cp.async.cg.shared.global [%0], [%1], 16;" :: "r"(d), "l"(src));
}
__device__ __forceinline__ void cp_commit() {
    asm volatile("cp.async.commit_group;");
}
__device__ __forceinline__ void cp_wait0() {
    asm volatile("cp.async.wait_group 0;");
}
__device__ __forceinline__ void mma_tf32(float* c, const uint32_t* a, const uint32_t* b) {
    asm volatile(
        "mma.sync.aligned.m16n8k8.row.col.f32.tf32.tf32.f32 "
        "{%0,%1,%2,%3}, {%4,%5,%6,%7}, {%8,%9}, {%0,%1,%2,%3};"
        : "+f"(c[0]), "+f"(c[1]), "+f"(c[2]), "+f"(c[3])
        : "r"(a[0]), "r"(a[1]), "r"(a[2]), "r"(a[3]), "r"(b[0]), "r"(b[1]));
}

template <bool TA, bool TB, bool BIAS, bool RES>
__global__ void __launch_bounds__(256, 2)
tgemm_kernel(int M, int N, int K,
             const float* __restrict__ A, int lda, size_t sA,
             const float* __restrict__ B, int ldb, size_t sB,
             float* __restrict__ Cp, int ldc, size_t sC,
             const float* __restrict__ bias,
             const float* __restrict__ res, size_t sR,
             float alpha)
{
    constexpr int BM = 128, BN = 128, BK = 16;
    // k-inner layout stride 20 (pad 4); k-outer layout stride 136 (pad 8)
    __shared__ float As[2][2560];
    __shared__ float Bs[2][2560];

    const int bz = blockIdx.z;
    A  += sA * bz;
    B  += sB * bz;
    Cp += sC * bz;
    if (RES) res += sR * bz;

    const int m0 = blockIdx.y * BM;
    const int n0 = blockIdx.x * BN;
    const int tid  = threadIdx.x;
    const int lane = tid & 31;
    const int wid  = tid >> 5;
    const int wm   = wid >> 1;       // 0..3 -> 32 rows each
    const int wn   = wid & 1;        // 0..1 -> 64 cols each
    const int grp  = lane >> 2;      // 0..7
    const int tig  = lane & 3;       // 0..3

    float acc[2][8][4];
    #pragma unroll
    for (int mi = 0; mi < 2; mi++)
        #pragma unroll
        for (int ni = 0; ni < 8; ni++)
            #pragma unroll
            for (int r = 0; r < 4; r++)
                acc[mi][ni][r] = 0.f;

    auto load_tiles = [&](int k0, int buf) {
        #pragma unroll
        for (int r = 0; r < 2; r++) {
            int idx = r * 256 + tid;
            if (!TA) {                      // A: M x K, smem m-major [128][20]
                int row = idx >> 2, ch = idx & 3;
                cp16(&As[buf][row * 20 + ch * 4],
                     A + (size_t)(m0 + row) * lda + k0 + ch * 4);
            } else {                        // A: K x M, smem k-major [16][136]
                int row = idx >> 5, ch = idx & 31;
                cp16(&As[buf][row * 136 + ch * 4],
                     A + (size_t)(k0 + row) * lda + m0 + ch * 4);
            }
        }
        #pragma unroll
        for (int r = 0; r < 2; r++) {
            int idx = r * 256 + tid;
            if (!TB) {                      // B: K x N, smem k-major [16][136]
                int row = idx >> 5, ch = idx & 31;
                cp16(&Bs[buf][row * 136 + ch * 4],
                     B + (size_t)(k0 + row) * ldb + n0 + ch * 4);
            } else {                        // B: N x K, smem n-major [128][20]
                int row = idx >> 2, ch = idx & 3;
                cp16(&Bs[buf][row * 20 + ch * 4],
                     B + (size_t)(n0 + row) * ldb + k0 + ch * 4);
            }
        }
    };

    const int nt = K / BK;
    load_tiles(0, 0);
    cp_commit();

    for (int t = 0; t < nt; t++) {
        cp_wait0();
        __syncthreads();
        const int cur = t & 1;
        if (t + 1 < nt) {
            load_tiles((t + 1) * BK, cur ^ 1);
            cp_commit();
        }

        #pragma unroll
        for (int ks = 0; ks < BK; ks += 8) {
            uint32_t af[2][4];
            #pragma unroll
            for (int mi = 0; mi < 2; mi++) {
                int m = wm * 32 + mi * 16 + grp;
                if (TA) {
                    af[mi][0] = f2tf(As[cur][(ks + tig)     * 136 + m]);
                    af[mi][1] = f2tf(As[cur][(ks + tig)     * 136 + m + 8]);
                    af[mi][2] = f2tf(As[cur][(ks + 4 + tig) * 136 + m]);
                    af[mi][3] = f2tf(As[cur][(ks + 4 + tig) * 136 + m + 8]);
                } else {
                    af[mi][0] = f2tf(As[cur][m       * 20 + ks + tig]);
                    af[mi][1] = f2tf(As[cur][(m + 8) * 20 + ks + tig]);
                    af[mi][2] = f2tf(As[cur][m       * 20 + ks + 4 + tig]);
                    af[mi][3] = f2tf(As[cur][(m + 8) * 20 + ks + 4 + tig]);
                }
            }
            uint32_t bf[8][2];
            #pragma unroll
            for (int ni = 0; ni < 8; ni++) {
                int n = wn * 64 + ni * 8 + grp;
                if (!TB) {
                    bf[ni][0] = f2tf(Bs[cur][(ks + tig)     * 136 + n]);
                    bf[ni][1] = f2tf(Bs[cur][(ks + 4 + tig) * 136 + n]);
                } else {
                    bf[ni][0] = f2tf(Bs[cur][n * 20 + ks + tig]);
                    bf[ni][1] = f2tf(Bs[cur][n * 20 + ks + 4 + tig]);
                }
            }
            #pragma unroll
            for (int mi = 0; mi < 2; mi++)
                #pragma unroll
                for (int ni = 0; ni < 8; ni++)
                    mma_tf32(acc[mi][ni], af[mi], bf[ni]);
        }
        __syncthreads();
    }

    // Epilogue: acc mapping (m16n8): rows grp, grp+8; cols tig*2, tig*2+1
    #pragma unroll
    for (int mi = 0; mi < 2; mi++) {
        int r0 = m0 + wm * 32 + mi * 16 + grp;
        int r1 = r0 + 8;
        float b0 = BIAS ? bias[r0] : 0.f;
        float b1 = BIAS ? bias[r1] : 0.f;
        #pragma unroll
        for (int ni = 0; ni < 8; ni++) {
            int c = n0 + wn * 64 + ni * 8 + tig * 2;
            float v0 = acc[mi][ni][0] * alpha + b0;
            float v1 = acc[mi][ni][1] * alpha + b0;
            float v2 = acc[mi][ni][2] * alpha + b1;
            float v3 = acc[mi][ni][3] * alpha + b1;
            if (RES) {
                v0 += res[(size_t)r0 * ldc + c];
                v1 += res[(size_t)r0 * ldc + c + 1];
                v2 += res[(size_t)r1 * ldc + c];
                v3 += res[(size_t)r1 * ldc + c + 1];
            }
            *(float2*)&Cp[(size_t)r0 * ldc + c] = make_float2(v0, v1);
            *(float2*)&Cp[(size_t)r1 * ldc + c] = make_float2(v2, v3);
        }
    }
}

// ---------------------------------------------------------------------------
// Row softmax
// ---------------------------------------------------------------------------
__global__ void __launch_bounds__(256)
softmax_kernel(float* __restrict__ attn)
{
    float* p = attn + (size_t)blockIdx.x * NPIX;
    const int tid = threadIdx.x;
    float lv[16];
    float mx = -1e30f;
    #pragma unroll
    for (int j = 0; j < 16; j++) {
        lv[j] = p[j * 256 + tid];
        mx = fmaxf(mx, lv[j]);
    }
    __shared__ float sh[8];
    #pragma unroll
    for (int o = 16; o; o >>= 1) mx = fmaxf(mx, __shfl_xor_sync(0xffffffffu, mx, o));
    if ((tid & 31) == 0) sh[tid >> 5] = mx;
    __syncthreads();
    if (tid < 32) {
        float v = ((tid & 31) < 8) ? sh[tid & 31] : -1e30f;
        #pragma unroll
        for (int o = 4; o; o >>= 1) v = fmaxf(v, __shfl_xor_sync(0xffffffffu, v, o));
        if (tid == 0) sh[0] = v;
    }
    __syncthreads();
    mx = sh[0];
    __syncthreads();

    float s = 0.f;
    #pragma unroll
    for (int j = 0; j < 16; j++) {
        lv[j] = __expf(lv[j] - mx);
        s += lv[j];
    }
    #pragma unroll
    for (int o = 16; o; o >>= 1) s += __shfl_xor_sync(0xffffffffu, s, o);
    if ((tid & 31) == 0) sh[tid >> 5] = s;
    __syncthreads();
    if (tid < 32) {
        float v = ((tid & 31) < 8) ? sh[tid & 31] : 0.f;
        #pragma unroll
        for (int o = 4; o; o >>= 1) v += __shfl_xor_sync(0xffffffffu, v, o);
        if (tid == 0) sh[0] = v;
    }
    __syncthreads();
    float inv = 1.f / sh[0];
    #pragma unroll
    for (int j = 0; j < 16; j++) p[j * 256 + tid] = lv[j] * inv;
}

// ---------------------------------------------------------------------------
// Launch
// ---------------------------------------------------------------------------
extern "C" void kernel_launch(void* const* d_in, const int* in_sizes, int n_in,
                              void* d_out, int out_size)
{
    const float* x        = (const float*)d_in[0];
    const float* gn_scale = (const float*)d_in[1];
    const float* gn_bias  = (const float*)d_in[2];
    const float* wq       = (const float*)d_in[3];
    const float* bq       = (const float*)d_in[4];
    const float* wk       = (const float*)d_in[5];
    const float* bk       = (const float*)d_in[6];
    const float* wv       = (const float*)d_in[7];
    const float* bv       = (const float*)d_in[8];
    const float* wp       = (const float*)d_in[9];
    const float* bp       = (const float*)d_in[10];
    float* out            = (float*)d_out;

    static float *hn = nullptr, *q, *k, *v, *attn, *o;
    if (!hn) {
        cudaGetSymbolAddress((void**)&hn,   g_hn);
        cudaGetSymbolAddress((void**)&q,    g_q);
        cudaGetSymbolAddress((void**)&k,    g_k);
        cudaGetSymbolAddress((void**)&v,    g_v);
        cudaGetSymbolAddress((void**)&attn, g_attn);
        cudaGetSymbolAddress((void**)&o,    g_o);
    }

    const size_t sCN = (size_t)CH * NPIX;
    const size_t sNN = (size_t)NPIX * NPIX;
    const float inv_sqrt_c = 0.044194173824159216f;

    groupnorm_kernel<<<BSZ * NGRP, 256>>>(x, gn_scale, gn_bias, hn);

    dim3 gQKV(NPIX / 128, CH / 128, BSZ);
    tgemm_kernel<false, false, true, false><<<gQKV, 256>>>(
        CH, NPIX, CH, wq, CH, 0, hn, NPIX, sCN, q, NPIX, sCN, bq, nullptr, 0, 1.f);
    tgemm_kernel<false, false, true, false><<<gQKV, 256>>>(
        CH, NPIX, CH, wk, CH, 0, hn, NPIX, sCN, k, NPIX, sCN, bk, nullptr, 0, 1.f);
    tgemm_kernel<false, false, true, false><<<gQKV, 256>>>(
        CH, NPIX, CH, wv, CH, 0, hn, NPIX, sCN, v, NPIX, sCN, bv, nullptr, 0, 1.f);

    dim3 gAtt(NPIX / 128, NPIX / 128, BSZ);
    tgemm_kernel<true, false, false, false><<<gAtt, 256>>>(
        NPIX, NPIX, CH, q, NPIX, sCN, k, NPIX, sCN, attn, NPIX, sNN,
        nullptr, nullptr, 0, inv_sqrt_c);

    softmax_kernel<<<BSZ * NPIX, 256>>>(attn);

    tgemm_kernel<false, true, false, false><<<gQKV, 256>>>(
        CH, NPIX, NPIX, v, NPIX, sCN, attn, NPIX, sNN, o, NPIX, sCN,
        nullptr, nullptr, 0, 1.f);

    tgemm_kernel<false, false, true, true><<<gQKV, 256>>>(
        CH, NPIX, CH, wp, CH, 0, o, NPIX, sCN, out, NPIX, sCN, bp, x, sCN, 1.f);
}

// round 4
// speedup vs baseline: 3.3092x; 1.1366x over previous
#include <cuda_runtime.h>
#include <math.h>
#include <stdint.h>

// ---------------------------------------------------------------------------
// AttentionBlock: GroupNorm -> QKV (1x1 conv) -> attention -> proj -> residual
// B=2, C=512, H=W=64 (N=4096), 32 groups, eps=1e-6
// Round 4: tf32 mma GEMMs, operands pre-rounded at producers (no cvt in
// mainloop), 3-stage cp.async pipeline, 1 sync per k-tile.
// ---------------------------------------------------------------------------

static constexpr int BSZ  = 2;
static constexpr int CH   = 512;
static constexpr int NPIX = 4096;
static constexpr int NGRP = 32;
static constexpr int CPG  = CH / NGRP;

__device__ float g_hn[(size_t)BSZ * CH * NPIX];
__device__ float g_q [(size_t)BSZ * CH * NPIX];
__device__ float g_k [(size_t)BSZ * CH * NPIX];
__device__ float g_v [(size_t)BSZ * CH * NPIX];
__device__ float g_o [(size_t)BSZ * CH * NPIX];
__device__ float g_attn[(size_t)BSZ * NPIX * NPIX];
__device__ float g_wq[CH * CH];
__device__ float g_wk[CH * CH];
__device__ float g_wv[CH * CH];
__device__ float g_wp[CH * CH];

__device__ __forceinline__ uint32_t f2tf(float x) {
    uint32_t r;
    asm("cvt.rna.tf32.f32 %0, %1;" : "=r"(r) : "f"(x));
    return r;
}
__device__ __forceinline__ float rnd_tf32(float x) {
    return __uint_as_float(f2tf(x));
}

// ---------------------------------------------------------------------------
// Round 4 weight matrices to tf32-valued fp32 (one-shot prep, 2^18 each)
// ---------------------------------------------------------------------------
__global__ void round_weights_kernel(const float* __restrict__ a, const float* __restrict__ b,
                                     const float* __restrict__ c, const float* __restrict__ d,
                                     float* __restrict__ oa, float* __restrict__ ob,
                                     float* __restrict__ oc, float* __restrict__ od)
{
    int i = blockIdx.x * blockDim.x + threadIdx.x;
    int w = i >> 18;
    int off = i & ((1 << 18) - 1);
    const float* src = (w == 0) ? a : (w == 1) ? b : (w == 2) ? c : d;
    float*       dst = (w == 0) ? oa : (w == 1) ? ob : (w == 2) ? oc : od;
    dst[off] = rnd_tf32(src[off]);
}

// ---------------------------------------------------------------------------
// GroupNorm (output rounded to tf32 values for GEMM consumption)
// ---------------------------------------------------------------------------
__global__ void groupnorm_kernel(const float* __restrict__ x,
                                 const float* __restrict__ scale,
                                 const float* __restrict__ bias,
                                 float* __restrict__ out)
{
    const int NPG = CPG * NPIX;
    const int g   = blockIdx.x & (NGRP - 1);
    const float* xp = x   + (size_t)blockIdx.x * NPG;
    float*       op = out + (size_t)blockIdx.x * NPG;

    float s = 0.f, ss = 0.f;
    for (int i = threadIdx.x; i < NPG; i += blockDim.x) {
        float v = xp[i];
        s += v; ss += v * v;
    }
    __shared__ float sh[64];
    #pragma unroll
    for (int o = 16; o; o >>= 1) {
        s  += __shfl_xor_sync(0xffffffffu, s,  o);
        ss += __shfl_xor_sync(0xffffffffu, ss, o);
    }
    int wid = threadIdx.x >> 5, lid = threadIdx.x & 31;
    if (lid == 0) { sh[wid] = s; sh[32 + wid] = ss; }
    __syncthreads();
    if (threadIdx.x < 32) {
        s  = (lid < 8) ? sh[lid]      : 0.f;
        ss = (lid < 8) ? sh[32 + lid] : 0.f;
        #pragma unroll
        for (int o = 4; o; o >>= 1) {
            s  += __shfl_xor_sync(0xffffffffu, s,  o);
            ss += __shfl_xor_sync(0xffffffffu, ss, o);
        }
        if (lid == 0) { sh[0] = s; sh[1] = ss; }
    }
    __syncthreads();
    float mean = sh[0] / (float)NPG;
    float var  = sh[1] / (float)NPG - mean * mean;
    float rstd = rsqrtf(var + 1e-6f);

    int cbase = g * CPG;
    for (int i = threadIdx.x; i < NPG; i += blockDim.x) {
        int c = cbase + (i >> 12);
        op[i] = rnd_tf32((xp[i] - mean) * rstd * scale[c] + bias[c]);
    }
}

// ---------------------------------------------------------------------------
// tf32 tensor-core GEMM, operands ALREADY tf32-valued in gmem.
//   C[m,n] = alpha * sum_k A(m,k)*B(k,n)  (+ bias[m]) (+ res[m,n])
//   TA: A stored K x M; else M x K.  TB: B stored N x K; else K x N.
//   RND: round epilogue stores to tf32 values (for downstream GEMMs).
// BM=BN=128, BK=16, 8 warps (4x2), warp tile 32x64, m16n8k8 tf32,
// 3-stage cp.async, one __syncthreads per k-tile.
// ---------------------------------------------------------------------------
__device__ __forceinline__ void cp16(float* dst, const float* src) {
    uint32_t d = (uint32_t)__cvta_generic_to_shared(dst);
    asm volatile("cp.async.cg.shared.global [%0], [%1], 16;" :: "r"(d), "l"(src));
}
__device__ __forceinline__ void cp_commit() { asm volatile("cp.async.commit_group;"); }
__device__ __forceinline__ void cp_wait1()  { asm volatile("cp.async.wait_group 1;"); }
__device__ __forceinline__ void mma_tf32(float* c, const uint32_t* a, const uint32_t* b) {
    asm volatile(
        "mma.sync.aligned.m16n8k8.row.col.f32.tf32.tf32.f32 "
        "{%0,%1,%2,%3}, {%4,%5,%6,%7}, {%8,%9}, {%0,%1,%2,%3};"
        : "+f"(c[0]), "+f"(c[1]), "+f"(c[2]), "+f"(c[3])
        : "r"(a[0]), "r"(a[1]), "r"(a[2]), "r"(a[3]), "r"(b[0]), "r"(b[1]));
}

static constexpr int STAGES = 3;
static constexpr int SBUF   = 2560;   // floats per stage per operand
static constexpr int GEMM_SMEM_BYTES = STAGES * 2 * SBUF * 4;   // 61440

template <bool TA, bool TB, bool BIAS, bool RES, bool RND>
__global__ void __launch_bounds__(256, 2)
tgemm_kernel(int M, int N, int K,
             const float* __restrict__ A, int lda, size_t sA,
             const float* __restrict__ B, int ldb, size_t sB,
             float* __restrict__ Cp, int ldc, size_t sC,
             const float* __restrict__ bias,
             const float* __restrict__ res, size_t sR,
             float alpha)
{
    constexpr int BM = 128, BN = 128, BK = 16;
    extern __shared__ float smem_[];
    float* Asm = smem_;                   // [STAGES][2560]
    float* Bsm = smem_ + STAGES * SBUF;   // [STAGES][2560]

    const int bz = blockIdx.z;
    A  += sA * bz;
    B  += sB * bz;
    Cp += sC * bz;
    if (RES) res += sR * bz;

    const int m0 = blockIdx.y * BM;
    const int n0 = blockIdx.x * BN;
    const int tid  = threadIdx.x;
    const int lane = tid & 31;
    const int wid  = tid >> 5;
    const int wm   = wid >> 1;
    const int wn   = wid & 1;
    const int grp  = lane >> 2;
    const int tig  = lane & 3;

    float acc[2][8][4];
    #pragma unroll
    for (int mi = 0; mi < 2; mi++)
        #pragma unroll
        for (int ni = 0; ni < 8; ni++)
            #pragma unroll
            for (int r = 0; r < 4; r++)
                acc[mi][ni][r] = 0.f;

    auto load_tiles = [&](int k0, int buf) {
        float* As = Asm + buf * SBUF;
        float* Bs = Bsm + buf * SBUF;
        #pragma unroll
        for (int r = 0; r < 2; r++) {
            int idx = r * 256 + tid;
            if (!TA) {                      // A: M x K -> smem m-major [128][20]
                int row = idx >> 2, ch = idx & 3;
                cp16(&As[row * 20 + ch * 4],
                     A + (size_t)(m0 + row) * lda + k0 + ch * 4);
            } else {                        // A: K x M -> smem k-major [16][136]
                int row = idx >> 5, ch = idx & 31;
                cp16(&As[row * 136 + ch * 4],
                     A + (size_t)(k0 + row) * lda + m0 + ch * 4);
            }
        }
        #pragma unroll
        for (int r = 0; r < 2; r++) {
            int idx = r * 256 + tid;
            if (!TB) {                      // B: K x N -> smem k-major [16][136]
                int row = idx >> 5, ch = idx & 31;
                cp16(&Bs[row * 136 + ch * 4],
                     B + (size_t)(k0 + row) * ldb + n0 + ch * 4);
            } else {                        // B: N x K -> smem n-major [128][20]
                int row = idx >> 2, ch = idx & 3;
                cp16(&Bs[row * 20 + ch * 4],
                     B + (size_t)(n0 + row) * ldb + k0 + ch * 4);
            }
        }
    };

    const int nt = K / BK;
    load_tiles(0, 0); cp_commit();
    load_tiles(BK, 1); cp_commit();

    for (int t = 0; t < nt; t++) {
        cp_wait1();
        __syncthreads();
        const int cur = t % STAGES;
        if (t + 2 < nt) load_tiles((t + 2) * BK, (t + 2) % STAGES);
        cp_commit();

        const float* As = Asm + cur * SBUF;
        const float* Bs = Bsm + cur * SBUF;
        #pragma unroll
        for (int ks = 0; ks < BK; ks += 8) {
            uint32_t af[2][4];
            #pragma unroll
            for (int mi = 0; mi < 2; mi++) {
                int m = wm * 32 + mi * 16 + grp;
                if (TA) {
                    af[mi][0] = __float_as_uint(As[(ks + tig)     * 136 + m]);
                    af[mi][1] = __float_as_uint(As[(ks + tig)     * 136 + m + 8]);
                    af[mi][2] = __float_as_uint(As[(ks + 4 + tig) * 136 + m]);
                    af[mi][3] = __float_as_uint(As[(ks + 4 + tig) * 136 + m + 8]);
                } else {
                    af[mi][0] = __float_as_uint(As[m       * 20 + ks + tig]);
                    af[mi][1] = __float_as_uint(As[(m + 8) * 20 + ks + tig]);
                    af[mi][2] = __float_as_uint(As[m       * 20 + ks + 4 + tig]);
                    af[mi][3] = __float_as_uint(As[(m + 8) * 20 + ks + 4 + tig]);
                }
            }
            uint32_t bf[8][2];
            #pragma unroll
            for (int ni = 0; ni < 8; ni++) {
                int n = wn * 64 + ni * 8 + grp;
                if (!TB) {
                    bf[ni][0] = __float_as_uint(Bs[(ks + tig)     * 136 + n]);
                    bf[ni][1] = __float_as_uint(Bs[(ks + 4 + tig) * 136 + n]);
                } else {
                    bf[ni][0] = __float_as_uint(Bs[n * 20 + ks + tig]);
                    bf[ni][1] = __float_as_uint(Bs[n * 20 + ks + 4 + tig]);
                }
            }
            #pragma unroll
            for (int mi = 0; mi < 2; mi++)
                #pragma unroll
                for (int ni = 0; ni < 8; ni++)
                    mma_tf32(acc[mi][ni], af[mi], bf[ni]);
        }
    }

    #pragma unroll
    for (int mi = 0; mi < 2; mi++) {
        int r0 = m0 + wm * 32 + mi * 16 + grp;
        int r1 = r0 + 8;
        float b0 = BIAS ? bias[r0] : 0.f;
        float b1 = BIAS ? bias[r1] : 0.f;
        #pragma unroll
        for (int ni = 0; ni < 8; ni++) {
            int c = n0 + wn * 64 + ni * 8 + tig * 2;
            float v0 = acc[mi][ni][0] * alpha + b0;
            float v1 = acc[mi][ni][1] * alpha + b0;
            float v2 = acc[mi][ni][2] * alpha + b1;
            float v3 = acc[mi][ni][3] * alpha + b1;
            if (RES) {
                v0 += res[(size_t)r0 * ldc + c];
                v1 += res[(size_t)r0 * ldc + c + 1];
                v2 += res[(size_t)r1 * ldc + c];
                v3 += res[(size_t)r1 * ldc + c + 1];
            }
            if (RND) {
                v0 = rnd_tf32(v0); v1 = rnd_tf32(v1);
                v2 = rnd_tf32(v2); v3 = rnd_tf32(v3);
            }
            *(float2*)&Cp[(size_t)r0 * ldc + c] = make_float2(v0, v1);
            *(float2*)&Cp[(size_t)r1 * ldc + c] = make_float2(v2, v3);
        }
    }
}

// ---------------------------------------------------------------------------
// Row softmax (float4 I/O; output rounded to tf32 values)
// ---------------------------------------------------------------------------
__global__ void __launch_bounds__(256)
softmax_kernel(float* __restrict__ attn)
{
    float4* p = (float4*)(attn + (size_t)blockIdx.x * NPIX);
    const int tid = threadIdx.x;
    float4 lv[4];
    float mx = -1e30f;
    #pragma unroll
    for (int j = 0; j < 4; j++) {
        lv[j] = p[j * 256 + tid];
        mx = fmaxf(fmaxf(fmaxf(mx, lv[j].x), fmaxf(lv[j].y, lv[j].z)), lv[j].w);
    }
    __shared__ float sh[8];
    #pragma unroll
    for (int o = 16; o; o >>= 1) mx = fmaxf(mx, __shfl_xor_sync(0xffffffffu, mx, o));
    if ((tid & 31) == 0) sh[tid >> 5] = mx;
    __syncthreads();
    if (tid < 32) {
        float v = (tid < 8) ? sh[tid] : -1e30f;
        #pragma unroll
        for (int o = 4; o; o >>= 1) v = fmaxf(v, __shfl_xor_sync(0xffffffffu, v, o));
        if (tid == 0) sh[0] = v;
    }
    __syncthreads();
    mx = sh[0];
    __syncthreads();

    float s = 0.f;
    #pragma unroll
    for (int j = 0; j < 4; j++) {
        lv[j].x = __expf(lv[j].x - mx); lv[j].y = __expf(lv[j].y - mx);
        lv[j].z = __expf(lv[j].z - mx); lv[j].w = __expf(lv[j].w - mx);
        s += lv[j].x + lv[j].y + lv[j].z + lv[j].w;
    }
    #pragma unroll
    for (int o = 16; o; o >>= 1) s += __shfl_xor_sync(0xffffffffu, s, o);
    if ((tid & 31) == 0) sh[tid >> 5] = s;
    __syncthreads();
    if (tid < 32) {
        float v = (tid < 8) ? sh[tid] : 0.f;
        #pragma unroll
        for (int o = 4; o; o >>= 1) v += __shfl_xor_sync(0xffffffffu, v, o);
        if (tid == 0) sh[0] = v;
    }
    __syncthreads();
    float inv = 1.f / sh[0];
    #pragma unroll
    for (int j = 0; j < 4; j++) {
        float4 w;
        w.x = rnd_tf32(lv[j].x * inv); w.y = rnd_tf32(lv[j].y * inv);
        w.z = rnd_tf32(lv[j].z * inv); w.w = rnd_tf32(lv[j].w * inv);
        p[j * 256 + tid] = w;
    }
}

// ---------------------------------------------------------------------------
// Launch
// ---------------------------------------------------------------------------
extern "C" void kernel_launch(void* const* d_in, const int* in_sizes, int n_in,
                              void* d_out, int out_size)
{
    const float* x        = (const float*)d_in[0];
    const float* gn_scale = (const float*)d_in[1];
    const float* gn_bias  = (const float*)d_in[2];
    const float* wq       = (const float*)d_in[3];
    const float* bq       = (const float*)d_in[4];
    const float* wk       = (const float*)d_in[5];
    const float* bk       = (const float*)d_in[6];
    const float* wv       = (const float*)d_in[7];
    const float* bv       = (const float*)d_in[8];
    const float* wp       = (const float*)d_in[9];
    const float* bp       = (const float*)d_in[10];
    float* out            = (float*)d_out;

    static float *hn = nullptr, *q, *k, *v, *attn, *o, *rwq, *rwk, *rwv, *rwp;
    if (!hn) {
        cudaGetSymbolAddress((void**)&hn,   g_hn);
        cudaGetSymbolAddress((void**)&q,    g_q);
        cudaGetSymbolAddress((void**)&k,    g_k);
        cudaGetSymbolAddress((void**)&v,    g_v);
        cudaGetSymbolAddress((void**)&attn, g_attn);
        cudaGetSymbolAddress((void**)&o,    g_o);
        cudaGetSymbolAddress((void**)&rwq,  g_wq);
        cudaGetSymbolAddress((void**)&rwk,  g_wk);
        cudaGetSymbolAddress((void**)&rwv,  g_wv);
        cudaGetSymbolAddress((void**)&rwp,  g_wp);
        // raise dynamic smem limit for all GEMM instantiations
        cudaFuncSetAttribute(tgemm_kernel<false, false, true,  false, true >,
                             cudaFuncAttributeMaxDynamicSharedMemorySize, GEMM_SMEM_BYTES);
        cudaFuncSetAttribute(tgemm_kernel<true,  false, false, false, false>,
                             cudaFuncAttributeMaxDynamicSharedMemorySize, GEMM_SMEM_BYTES);
        cudaFuncSetAttribute(tgemm_kernel<false, true,  false, false, true >,
                             cudaFuncAttributeMaxDynamicSharedMemorySize, GEMM_SMEM_BYTES);
        cudaFuncSetAttribute(tgemm_kernel<false, false, true,  true,  false>,
                             cudaFuncAttributeMaxDynamicSharedMemorySize, GEMM_SMEM_BYTES);
    }

    const size_t sCN = (size_t)CH * NPIX;
    const size_t sNN = (size_t)NPIX * NPIX;
    const float inv_sqrt_c = 0.044194173824159216f;

    round_weights_kernel<<<4 * CH * CH / 256, 256>>>(wq, wk, wv, wp, rwq, rwk, rwv, rwp);
    groupnorm_kernel<<<BSZ * NGRP, 256>>>(x, gn_scale, gn_bias, hn);

    dim3 gQKV(NPIX / 128, CH / 128, BSZ);
    tgemm_kernel<false, false, true, false, true><<<gQKV, 256, GEMM_SMEM_BYTES>>>(
        CH, NPIX, CH, rwq, CH, 0, hn, NPIX, sCN, q, NPIX, sCN, bq, nullptr, 0, 1.f);
    tgemm_kernel<false, false, true, false, true><<<gQKV, 256, GEMM_SMEM_BYTES>>>(
        CH, NPIX, CH, rwk, CH, 0, hn, NPIX, sCN, k, NPIX, sCN, bk, nullptr, 0, 1.f);
    tgemm_kernel<false, false, true, false, true><<<gQKV, 256, GEMM_SMEM_BYTES>>>(
        CH, NPIX, CH, rwv, CH, 0, hn, NPIX, sCN, v, NPIX, sCN, bv, nullptr, 0, 1.f);

    dim3 gAtt(NPIX / 128, NPIX / 128, BSZ);
    tgemm_kernel<true, false, false, false, false><<<gAtt, 256, GEMM_SMEM_BYTES>>>(
        NPIX, NPIX, CH, q, NPIX, sCN, k, NPIX, sCN, attn, NPIX, sNN,
        nullptr, nullptr, 0, inv_sqrt_c);

    softmax_kernel<<<BSZ * NPIX, 256>>>(attn);

    tgemm_kernel<false, true, false, false, true><<<gQKV, 256, GEMM_SMEM_BYTES>>>(
        CH, NPIX, NPIX, v, NPIX, sCN, attn, NPIX, sNN, o, NPIX, sCN,
        nullptr, nullptr, 0, 1.f);

    tgemm_kernel<false, false, true, true, false><<<gQKV, 256, GEMM_SMEM_BYTES>>>(
        CH, NPIX, CH, rwp, CH, 0, o, NPIX, sCN, out, NPIX, sCN, bp, x, sCN, 1.f);
}

// round 9
// speedup vs baseline: 3.7706x; 1.1394x over previous
#include <cuda_runtime.h>
#include <cuda_bf16.h>
#include <math.h>
#include <stdint.h>

// ---------------------------------------------------------------------------
// AttentionBlock, legacy-HMMA bf16 path (tcgen05 unavailable: harness ptxas
// targets plain sm_103). B=2, C=512, N=4096, 32 groups.
// All five GEMMs: D[M,N] = A[M,K] . B[N,K]^T, bf16 inputs, fp32 accum,
// mma.m16n8k16 + ldmatrix.x4, 3-stage cp.async.
// K-contiguous data plan: hnT[n,c], qT[n,c], kT[n,c], v[c,n], probs[i,j],
// oT[i,c], out[c,n].
// ---------------------------------------------------------------------------

static constexpr int BSZ  = 2;
static constexpr int CH   = 512;
static constexpr int NPIX = 4096;
static constexpr int NGRP = 32;

typedef __nv_bfloat16 bf16;

__device__ bf16  g_hn[(size_t)BSZ * CH * NPIX];        // hnT [b][n][c]
__device__ bf16  g_q [(size_t)BSZ * CH * NPIX];        // qT  [b][n][c]
__device__ bf16  g_k [(size_t)BSZ * CH * NPIX];        // kT  [b][n][c]
__device__ bf16  g_v [(size_t)BSZ * CH * NPIX];        // v   [b][c][n]
__device__ bf16  g_o [(size_t)BSZ * CH * NPIX];        // oT  [b][n][c]
__device__ float g_attn[(size_t)BSZ * NPIX * NPIX];    // logits fp32
__device__ bf16  g_p [(size_t)BSZ * NPIX * NPIX];      // probs bf16
__device__ bf16  g_wq[CH * CH];
__device__ bf16  g_wk[CH * CH];
__device__ bf16  g_wv[CH * CH];
__device__ bf16  g_wp[CH * CH];
__device__ float g_stats[BSZ * NGRP * 2];

// ---------------------------------------------------------------------------
// helpers
// ---------------------------------------------------------------------------
__device__ __forceinline__ uint32_t smem_u32(const void* p) {
    return (uint32_t)__cvta_generic_to_shared(p);
}
__device__ __forceinline__ void cp16(void* dst, const void* src) {
    asm volatile("cp.async.cg.shared.global [%0], [%1], 16;"
                 :: "r"(smem_u32(dst)), "l"(src));
}
__device__ __forceinline__ void cp_commit() { asm volatile("cp.async.commit_group;"); }
__device__ __forceinline__ void cp_wait1()  { asm volatile("cp.async.wait_group 1;"); }

__device__ __forceinline__ void ldsm_x4(uint32_t& r0, uint32_t& r1,
                                        uint32_t& r2, uint32_t& r3, uint32_t a) {
    asm volatile("ldmatrix.sync.aligned.m8n8.x4.shared.b16 {%0,%1,%2,%3}, [%4];"
                 : "=r"(r0), "=r"(r1), "=r"(r2), "=r"(r3) : "r"(a));
}
__device__ __forceinline__ void mma_bf16(float* c, const uint32_t* a, const uint32_t* b) {
    asm volatile(
        "mma.sync.aligned.m16n8k16.row.col.f32.bf16.bf16.f32 "
        "{%0,%1,%2,%3}, {%4,%5,%6,%7}, {%8,%9}, {%0,%1,%2,%3};"
        : "+f"(c[0]), "+f"(c[1]), "+f"(c[2]), "+f"(c[3])
        : "r"(a[0]), "r"(a[1]), "r"(a[2]), "r"(a[3]), "r"(b[0]), "r"(b[1]));
}

// ---------------------------------------------------------------------------
// weight rounding fp32 -> bf16
// ---------------------------------------------------------------------------
__global__ void round_weights_kernel(const float* __restrict__ a, const float* __restrict__ b,
                                     const float* __restrict__ c, const float* __restrict__ d,
                                     bf16* __restrict__ oa, bf16* __restrict__ ob,
                                     bf16* __restrict__ oc, bf16* __restrict__ od)
{
    int i = blockIdx.x * blockDim.x + threadIdx.x;
    int w = i >> 18;
    int off = i & ((1 << 18) - 1);
    const float* src = (w == 0) ? a : (w == 1) ? b : (w == 2) ? c : d;
    bf16*        dst = (w == 0) ? oa : (w == 1) ? ob : (w == 2) ? oc : od;
    dst[off] = __float2bfloat16_rn(src[off]);
}

// ---------------------------------------------------------------------------
// GroupNorm stats
// ---------------------------------------------------------------------------
__global__ void gn_stats_kernel(const float* __restrict__ x, float* __restrict__ stats)
{
    const int NPG = (CH / NGRP) * NPIX;
    const float* xp = x + (size_t)blockIdx.x * NPG;
    float s = 0.f, ss = 0.f;
    for (int i = threadIdx.x; i < NPG; i += blockDim.x) {
        float v = xp[i];
        s += v; ss += v * v;
    }
    __shared__ float sh[64];
    #pragma unroll
    for (int o = 16; o; o >>= 1) {
        s  += __shfl_xor_sync(0xffffffffu, s,  o);
        ss += __shfl_xor_sync(0xffffffffu, ss, o);
    }
    int wid = threadIdx.x >> 5, lid = threadIdx.x & 31;
    if (lid == 0) { sh[wid] = s; sh[32 + wid] = ss; }
    __syncthreads();
    if (threadIdx.x < 32) {
        s  = (lid < 8) ? sh[lid]      : 0.f;
        ss = (lid < 8) ? sh[32 + lid] : 0.f;
        #pragma unroll
        for (int o = 4; o; o >>= 1) {
            s  += __shfl_xor_sync(0xffffffffu, s,  o);
            ss += __shfl_xor_sync(0xffffffffu, ss, o);
        }
        if (lid == 0) {
            float mean = s / (float)NPG;
            float var  = ss / (float)NPG - mean * mean;
            stats[blockIdx.x * 2 + 0] = mean;
            stats[blockIdx.x * 2 + 1] = rsqrtf(var + 1e-6f);
        }
    }
}

// ---------------------------------------------------------------------------
// Normalize + transpose: x[b][c][n] -> hnT[b][n][c] (bf16)
// ---------------------------------------------------------------------------
__global__ void __launch_bounds__(256)
gn_transpose_kernel(const float* __restrict__ x, const float* __restrict__ stats,
                    const float* __restrict__ scale, const float* __restrict__ bias,
                    bf16* __restrict__ hnT)
{
    __shared__ float tile[32][33];
    const int n0 = blockIdx.x * 32;
    const int c0 = blockIdx.y * 32;
    const int b  = blockIdx.z;
    const float* xb = x + (size_t)b * CH * NPIX;
    bf16* hb = hnT + (size_t)b * NPIX * CH;

    #pragma unroll
    for (int r = 0; r < 4; r++) {
        int idx = r * 256 + threadIdx.x;
        int ci = idx >> 5, nj = idx & 31;
        int c = c0 + ci;
        int g = c >> 4;
        float mean = stats[(b * NGRP + g) * 2 + 0];
        float rstd = stats[(b * NGRP + g) * 2 + 1];
        float v = xb[(size_t)c * NPIX + n0 + nj];
        tile[ci][nj] = (v - mean) * rstd * scale[c] + bias[c];
    }
    __syncthreads();
    #pragma unroll
    for (int r = 0; r < 2; r++) {
        int idx = r * 256 + threadIdx.x;
        int ni = idx >> 4, cj = (idx & 15) * 2;
        __nv_bfloat162 w;
        w.x = __float2bfloat16_rn(tile[cj][ni]);
        w.y = __float2bfloat16_rn(tile[cj + 1][ni]);
        *(__nv_bfloat162*)&hb[(size_t)(n0 + ni) * CH + c0 + cj] = w;
    }
}

// ---------------------------------------------------------------------------
// bf16 HMMA GEMM: D[M,N] = alpha * A[M,K].B[N,K]^T (+bias)(+res)
// BM=BN=128, BK=32, 8 warps (4x2), warp tile 32x64, m16n8k16,
// ldmatrix.x4 from 80B-strided smem rows (conflict-free), 3-stage cp.async.
// BIAS_MODE: 0 none, 1 bias[m], 2 bias[n].  OUT_BF: bf16 vs fp32 output.
// ---------------------------------------------------------------------------
static constexpr int ROWE  = 40;                 // row stride in bf16 elems (80B)
static constexpr int SELEM = 128 * ROWE;         // 5120 elems per operand per stage
static constexpr int GEMM_SMEM = 3 * 2 * SELEM * 2;   // 61440 bytes

template <int BIAS_MODE, bool RES, bool OUT_BF>
__global__ void __launch_bounds__(256)
hgemm(int K,
      const bf16* __restrict__ A, int lda, size_t sA,
      const bf16* __restrict__ B, int ldb, size_t sB,
      void* __restrict__ Cvp, int ldc, size_t sC,
      const float* __restrict__ bias,
      const float* __restrict__ res, size_t sR,
      float alpha)
{
    extern __shared__ bf16 smem[];
    const int bz = blockIdx.z;
    A += sA * bz;
    B += sB * bz;
    if (RES) res += sR * bz;

    const int m0 = blockIdx.y * 128;
    const int n0 = blockIdx.x * 128;
    const int tid  = threadIdx.x;
    const int lane = tid & 31;
    const int wid  = tid >> 5;
    const int wm   = wid >> 1;
    const int wn   = wid & 1;
    const int grp  = lane >> 2;
    const int tig  = lane & 3;

    float acc[2][8][4];
    #pragma unroll
    for (int mi = 0; mi < 2; mi++)
        #pragma unroll
        for (int ni = 0; ni < 8; ni++)
            #pragma unroll
            for (int r = 0; r < 4; r++)
                acc[mi][ni][r] = 0.f;

    auto load_tile = [&](int k0, int st) {
        bf16* As = smem + st * 2 * SELEM;
        bf16* Bs = As + SELEM;
        #pragma unroll
        for (int r = 0; r < 2; r++) {
            int idx = r * 256 + tid;
            int row = idx >> 2, c = idx & 3;          // 4x16B chunks per row
            cp16(&As[row * ROWE + c * 8], A + (size_t)(m0 + row) * lda + k0 + c * 8);
        }
        #pragma unroll
        for (int r = 0; r < 2; r++) {
            int idx = r * 256 + tid;
            int row = idx >> 2, c = idx & 3;
            cp16(&Bs[row * ROWE + c * 8], B + (size_t)(n0 + row) * ldb + k0 + c * 8);
        }
    };

    const int nt = K / 32;
    load_tile(0, 0);  cp_commit();
    load_tile(32, 1); cp_commit();

    // lane->ldmatrix source row/col (same formula for A and B tiles)
    const int lrow = lane & 15;
    const int lkof = (lane >> 4) << 3;

    for (int t = 0; t < nt; t++) {
        cp_wait1();
        __syncthreads();
        const int st = t % 3;
        if (t + 2 < nt) load_tile((t + 2) * 32, (t + 2) % 3);
        cp_commit();

        const bf16* As = smem + st * 2 * SELEM;
        const bf16* Bs = As + SELEM;

        #pragma unroll
        for (int ks = 0; ks < 32; ks += 16) {
            uint32_t af[2][4];
            #pragma unroll
            for (int mi = 0; mi < 2; mi++) {
                int row = wm * 32 + mi * 16 + lrow;
                uint32_t a = smem_u32(&As[row * ROWE + ks + lkof]);
                ldsm_x4(af[mi][0], af[mi][1], af[mi][2], af[mi][3], a);
            }
            uint32_t bfr[8][2];
            #pragma unroll
            for (int nb = 0; nb < 4; nb++) {
                int row = wn * 64 + nb * 16 + lrow;
                uint32_t a = smem_u32(&Bs[row * ROWE + ks + lkof]);
                uint32_t r0, r1, r2, r3;
                ldsm_x4(r0, r1, r2, r3, a);
                bfr[nb * 2][0] = r0; bfr[nb * 2][1] = r2;
                bfr[nb * 2 + 1][0] = r1; bfr[nb * 2 + 1][1] = r3;
            }
            #pragma unroll
            for (int mi = 0; mi < 2; mi++)
                #pragma unroll
                for (int ni = 0; ni < 8; ni++)
                    mma_bf16(acc[mi][ni], af[mi], bfr[ni]);
        }
        __syncthreads();
    }

    // epilogue (rows grp/grp+8, cols tig*2..+1 per n-frag)
    #pragma unroll
    for (int mi = 0; mi < 2; mi++) {
        int r0 = m0 + wm * 32 + mi * 16 + grp;
        int r1 = r0 + 8;
        float brow0 = (BIAS_MODE == 1) ? bias[r0] : 0.f;
        float brow1 = (BIAS_MODE == 1) ? bias[r1] : 0.f;
        #pragma unroll
        for (int ni = 0; ni < 8; ni++) {
            int c = n0 + wn * 64 + ni * 8 + tig * 2;
            float v0 = acc[mi][ni][0] * alpha;
            float v1 = acc[mi][ni][1] * alpha;
            float v2 = acc[mi][ni][2] * alpha;
            float v3 = acc[mi][ni][3] * alpha;
            if (BIAS_MODE == 1) { v0 += brow0; v1 += brow0; v2 += brow1; v3 += brow1; }
            if (BIAS_MODE == 2) {
                float bc0 = bias[c], bc1 = bias[c + 1];
                v0 += bc0; v1 += bc1; v2 += bc0; v3 += bc1;
            }
            if (RES) {
                v0 += res[(size_t)r0 * ldc + c];
                v1 += res[(size_t)r0 * ldc + c + 1];
                v2 += res[(size_t)r1 * ldc + c];
                v3 += res[(size_t)r1 * ldc + c + 1];
            }
            if (OUT_BF) {
                bf16* Cp = (bf16*)Cvp + sC * bz;
                __nv_bfloat162 w0, w1;
                w0.x = __float2bfloat16_rn(v0); w0.y = __float2bfloat16_rn(v1);
                w1.x = __float2bfloat16_rn(v2); w1.y = __float2bfloat16_rn(v3);
                *(__nv_bfloat162*)&Cp[(size_t)r0 * ldc + c] = w0;
                *(__nv_bfloat162*)&Cp[(size_t)r1 * ldc + c] = w1;
            } else {
                float* Cp = (float*)Cvp + sC * bz;
                *(float2*)&Cp[(size_t)r0 * ldc + c] = make_float2(v0, v1);
                *(float2*)&Cp[(size_t)r1 * ldc + c] = make_float2(v2, v3);
            }
        }
    }
}

// ---------------------------------------------------------------------------
// Row softmax: fp32 logits in, bf16 probs out
// ---------------------------------------------------------------------------
__global__ void __launch_bounds__(256)
softmax_kernel(const float* __restrict__ attn, bf16* __restrict__ probs)
{
    const float4* p = (const float4*)(attn + (size_t)blockIdx.x * NPIX);
    bf16* po = probs + (size_t)blockIdx.x * NPIX;
    const int tid = threadIdx.x;
    float4 lv[4];
    float mx = -1e30f;
    #pragma unroll
    for (int j = 0; j < 4; j++) {
        lv[j] = p[j * 256 + tid];
        mx = fmaxf(fmaxf(fmaxf(mx, lv[j].x), fmaxf(lv[j].y, lv[j].z)), lv[j].w);
    }
    __shared__ float sh[8];
    #pragma unroll
    for (int o = 16; o; o >>= 1) mx = fmaxf(mx, __shfl_xor_sync(0xffffffffu, mx, o));
    if ((tid & 31) == 0) sh[tid >> 5] = mx;
    __syncthreads();
    if (tid < 32) {
        float v = (tid < 8) ? sh[tid] : -1e30f;
        #pragma unroll
        for (int o = 4; o; o >>= 1) v = fmaxf(v, __shfl_xor_sync(0xffffffffu, v, o));
        if (tid == 0) sh[0] = v;
    }
    __syncthreads();
    mx = sh[0];
    __syncthreads();

    float s = 0.f;
    #pragma unroll
    for (int j = 0; j < 4; j++) {
        lv[j].x = __expf(lv[j].x - mx); lv[j].y = __expf(lv[j].y - mx);
        lv[j].z = __expf(lv[j].z - mx); lv[j].w = __expf(lv[j].w - mx);
        s += lv[j].x + lv[j].y + lv[j].z + lv[j].w;
    }
    #pragma unroll
    for (int o = 16; o; o >>= 1) s += __shfl_xor_sync(0xffffffffu, s, o);
    if ((tid & 31) == 0) sh[tid >> 5] = s;
    __syncthreads();
    if (tid < 32) {
        float v = (tid < 8) ? sh[tid] : 0.f;
        #pragma unroll
        for (int o = 4; o; o >>= 1) v += __shfl_xor_sync(0xffffffffu, v, o);
        if (tid == 0) sh[0] = v;
    }
    __syncthreads();
    float inv = 1.f / sh[0];
    #pragma unroll
    for (int j = 0; j < 4; j++) {
        __nv_bfloat162 w0, w1;
        w0.x = __float2bfloat16_rn(lv[j].x * inv);
        w0.y = __float2bfloat16_rn(lv[j].y * inv);
        w1.x = __float2bfloat16_rn(lv[j].z * inv);
        w1.y = __float2bfloat16_rn(lv[j].w * inv);
        *(__nv_bfloat162*)&po[(j * 256 + tid) * 4]     = w0;
        *(__nv_bfloat162*)&po[(j * 256 + tid) * 4 + 2] = w1;
    }
}

// ---------------------------------------------------------------------------
// Launch
// ---------------------------------------------------------------------------
extern "C" void kernel_launch(void* const* d_in, const int* in_sizes, int n_in,
                              void* d_out, int out_size)
{
    const float* x        = (const float*)d_in[0];
    const float* gn_scale = (const float*)d_in[1];
    const float* gn_bias  = (const float*)d_in[2];
    const float* wq       = (const float*)d_in[3];
    const float* bq       = (const float*)d_in[4];
    const float* wk       = (const float*)d_in[5];
    const float* bk       = (const float*)d_in[6];
    const float* wv       = (const float*)d_in[7];
    const float* bv       = (const float*)d_in[8];
    const float* wp       = (const float*)d_in[9];
    const float* bp       = (const float*)d_in[10];
    float* out            = (float*)d_out;

    static bf16 *hnT = nullptr, *qT, *kT, *v, *probs, *oT, *rwq, *rwk, *rwv, *rwp;
    static float *attn, *stats;
    if (!hnT) {
        cudaGetSymbolAddress((void**)&hnT,  g_hn);
        cudaGetSymbolAddress((void**)&qT,   g_q);
        cudaGetSymbolAddress((void**)&kT,   g_k);
        cudaGetSymbolAddress((void**)&v,    g_v);
        cudaGetSymbolAddress((void**)&probs,g_p);
        cudaGetSymbolAddress((void**)&oT,   g_o);
        cudaGetSymbolAddress((void**)&attn, g_attn);
        cudaGetSymbolAddress((void**)&rwq,  g_wq);
        cudaGetSymbolAddress((void**)&rwk,  g_wk);
        cudaGetSymbolAddress((void**)&rwv,  g_wv);
        cudaGetSymbolAddress((void**)&rwp,  g_wp);
        cudaGetSymbolAddress((void**)&stats, g_stats);
        cudaFuncSetAttribute(hgemm<2, false, true >,
                             cudaFuncAttributeMaxDynamicSharedMemorySize, GEMM_SMEM);
        cudaFuncSetAttribute(hgemm<1, false, true >,
                             cudaFuncAttributeMaxDynamicSharedMemorySize, GEMM_SMEM);
        cudaFuncSetAttribute(hgemm<0, false, false>,
                             cudaFuncAttributeMaxDynamicSharedMemorySize, GEMM_SMEM);
        cudaFuncSetAttribute(hgemm<0, false, true >,
                             cudaFuncAttributeMaxDynamicSharedMemorySize, GEMM_SMEM);
        cudaFuncSetAttribute(hgemm<1, true,  false>,
                             cudaFuncAttributeMaxDynamicSharedMemorySize, GEMM_SMEM);
    }

    const size_t sCN = (size_t)CH * NPIX;
    const size_t sNN = (size_t)NPIX * NPIX;
    const float inv_sqrt_c = 0.044194173824159216f;   // 1/sqrt(512)

    round_weights_kernel<<<4 * CH * CH / 256, 256>>>(wq, wk, wv, wp, rwq, rwk, rwv, rwp);
    gn_stats_kernel<<<BSZ * NGRP, 256>>>(x, stats);
    gn_transpose_kernel<<<dim3(NPIX / 32, CH / 32, BSZ), 256>>>(x, stats, gn_scale, gn_bias, hnT);

    // qT[n,d] = hnT[n,:] . Wq[d,:] + bq[d]   (M=4096, N=512, K=512)
    hgemm<2, false, true><<<dim3(CH / 128, NPIX / 128, BSZ), 256, GEMM_SMEM>>>(
        CH, hnT, CH, sCN, rwq, CH, 0, qT, CH, sCN, bq, nullptr, 0, 1.f);
    hgemm<2, false, true><<<dim3(CH / 128, NPIX / 128, BSZ), 256, GEMM_SMEM>>>(
        CH, hnT, CH, sCN, rwk, CH, 0, kT, CH, sCN, bk, nullptr, 0, 1.f);
    // v[d,n] = Wv[d,:] . hnT[n,:] + bv[d]    (M=512, N=4096, K=512)
    hgemm<1, false, true><<<dim3(NPIX / 128, CH / 128, BSZ), 256, GEMM_SMEM>>>(
        CH, rwv, CH, 0, hnT, CH, sCN, v, NPIX, sCN, bv, nullptr, 0, 1.f);

    // logits[i,j] = alpha * qT[i,:] . kT[j,:]   (M=N=4096, K=512)
    hgemm<0, false, false><<<dim3(NPIX / 128, NPIX / 128, BSZ), 256, GEMM_SMEM>>>(
        CH, qT, CH, sCN, kT, CH, sCN, attn, NPIX, sNN, nullptr, nullptr, 0, inv_sqrt_c);

    softmax_kernel<<<BSZ * NPIX, 256>>>(attn, probs);

    // oT[i,c] = probs[i,:] . v[c,:]   (M=4096, N=512, K=4096)
    hgemm<0, false, true><<<dim3(CH / 128, NPIX / 128, BSZ), 256, GEMM_SMEM>>>(
        NPIX, probs, NPIX, sNN, v, NPIX, sCN, oT, CH, sCN, nullptr, nullptr, 0, 1.f);

    // out[d,n] = Wp[d,:] . oT[n,:] + bp[d] + x[d,n]   (M=512, N=4096, K=512)
    hgemm<1, true, false><<<dim3(NPIX / 128, CH / 128, BSZ), 256, GEMM_SMEM>>>(
        CH, rwp, CH, 0, oT, CH, sCN, out, NPIX, sCN, bp, x, sCN, 1.f);
}

// round 10
// speedup vs baseline: 5.6108x; 1.4880x over previous
#include <cuda_runtime.h>
#include <cuda_bf16.h>
#include <math.h>
#include <stdint.h>

// ---------------------------------------------------------------------------
// AttentionBlock, legacy-HMMA bf16 (tcgen05 unavailable: harness ptxas targets
// plain sm_103). B=2, C=512, N=4096, 32 groups.
// R10: BN-templated GEMM (64 for N=512 shapes -> 2-4x grid, occ 3 CTA/SM;
// 128 for QK), 4-stage cp.async + single sync/iter, fused Q+K GEMM.
// D[M,N] = alpha * A[M,K] . B[N,K]^T, bf16 in, fp32 accum.
// ---------------------------------------------------------------------------

static constexpr int BSZ  = 2;
static constexpr int CH   = 512;
static constexpr int NPIX = 4096;
static constexpr int NGRP = 32;

typedef __nv_bfloat16 bf16;

__device__ bf16  g_hn[(size_t)BSZ * CH * NPIX];          // hnT [b][n][c]
__device__ bf16  g_qk[(size_t)BSZ * NPIX * 2 * CH];      // qkT [b][n][1024]
__device__ bf16  g_v [(size_t)BSZ * CH * NPIX];          // v   [b][c][n]
__device__ bf16  g_o [(size_t)BSZ * CH * NPIX];          // oT  [b][n][c]
__device__ float g_attn[(size_t)BSZ * NPIX * NPIX];      // logits fp32
__device__ bf16  g_p [(size_t)BSZ * NPIX * NPIX];        // probs bf16
__device__ bf16  g_wqk[2 * CH * CH];                     // [Wq; Wk] bf16
__device__ bf16  g_wv[CH * CH];
__device__ bf16  g_wp[CH * CH];
__device__ float g_bqk[2 * CH];
__device__ float g_stats[BSZ * NGRP * 2];

// ---------------------------------------------------------------------------
__device__ __forceinline__ uint32_t smem_u32(const void* p) {
    return (uint32_t)__cvta_generic_to_shared(p);
}
__device__ __forceinline__ void cp16(void* dst, const void* src) {
    asm volatile("cp.async.cg.shared.global [%0], [%1], 16;"
                 :: "r"(smem_u32(dst)), "l"(src));
}
__device__ __forceinline__ void cp_commit() { asm volatile("cp.async.commit_group;"); }
__device__ __forceinline__ void cp_wait2()  { asm volatile("cp.async.wait_group 2;"); }

__device__ __forceinline__ void ldsm_x4(uint32_t& r0, uint32_t& r1,
                                        uint32_t& r2, uint32_t& r3, uint32_t a) {
    asm volatile("ldmatrix.sync.aligned.m8n8.x4.shared.b16 {%0,%1,%2,%3}, [%4];"
                 : "=r"(r0), "=r"(r1), "=r"(r2), "=r"(r3) : "r"(a));
}
__device__ __forceinline__ void mma_bf16(float* c, const uint32_t* a, const uint32_t* b) {
    asm volatile(
        "mma.sync.aligned.m16n8k16.row.col.f32.bf16.bf16.f32 "
        "{%0,%1,%2,%3}, {%4,%5,%6,%7}, {%8,%9}, {%0,%1,%2,%3};"
        : "+f"(c[0]), "+f"(c[1]), "+f"(c[2]), "+f"(c[3])
        : "r"(a[0]), "r"(a[1]), "r"(a[2]), "r"(a[3]), "r"(b[0]), "r"(b[1]));
}

// ---------------------------------------------------------------------------
// prep: weights -> bf16 (wq,wk concatenated), biases bq|bk -> fp32 concat
// ---------------------------------------------------------------------------
__global__ void round_weights_kernel(const float* __restrict__ a, const float* __restrict__ b,
                                     const float* __restrict__ c, const float* __restrict__ d,
                                     bf16* __restrict__ wqk, bf16* __restrict__ wv,
                                     bf16* __restrict__ wp)
{
    int i = blockIdx.x * blockDim.x + threadIdx.x;
    int w = i >> 18;
    int off = i & ((1 << 18) - 1);
    const float* src = (w == 0) ? a : (w == 1) ? b : (w == 2) ? c : d;
    bf16* dst = (w == 0) ? wqk : (w == 1) ? (wqk + CH * CH) : (w == 2) ? wv : wp;
    dst[off] = __float2bfloat16_rn(src[off]);
}
__global__ void bias_concat_kernel(const float* __restrict__ bq,
                                   const float* __restrict__ bk,
                                   float* __restrict__ o)
{
    int i = blockIdx.x * blockDim.x + threadIdx.x;
    o[i] = (i < CH) ? bq[i] : bk[i - CH];
}

// ---------------------------------------------------------------------------
// GroupNorm stats
// ---------------------------------------------------------------------------
__global__ void gn_stats_kernel(const float* __restrict__ x, float* __restrict__ stats)
{
    const int NPG = (CH / NGRP) * NPIX;
    const float* xp = x + (size_t)blockIdx.x * NPG;
    float s = 0.f, ss = 0.f;
    for (int i = threadIdx.x; i < NPG; i += blockDim.x) {
        float v = xp[i];
        s += v; ss += v * v;
    }
    __shared__ float sh[64];
    #pragma unroll
    for (int o = 16; o; o >>= 1) {
        s  += __shfl_xor_sync(0xffffffffu, s,  o);
        ss += __shfl_xor_sync(0xffffffffu, ss, o);
    }
    int wid = threadIdx.x >> 5, lid = threadIdx.x & 31;
    if (lid == 0) { sh[wid] = s; sh[32 + wid] = ss; }
    __syncthreads();
    if (threadIdx.x < 32) {
        s  = (lid < 8) ? sh[lid]      : 0.f;
        ss = (lid < 8) ? sh[32 + lid] : 0.f;
        #pragma unroll
        for (int o = 4; o; o >>= 1) {
            s  += __shfl_xor_sync(0xffffffffu, s,  o);
            ss += __shfl_xor_sync(0xffffffffu, ss, o);
        }
        if (lid == 0) {
            float mean = s / (float)NPG;
            float var  = ss / (float)NPG - mean * mean;
            stats[blockIdx.x * 2 + 0] = mean;
            stats[blockIdx.x * 2 + 1] = rsqrtf(var + 1e-6f);
        }
    }
}

// ---------------------------------------------------------------------------
// Normalize + transpose: x[b][c][n] -> hnT[b][n][c] bf16
// ---------------------------------------------------------------------------
__global__ void __launch_bounds__(256)
gn_transpose_kernel(const float* __restrict__ x, const float* __restrict__ stats,
                    const float* __restrict__ scale, const float* __restrict__ bias,
                    bf16* __restrict__ hnT)
{
    __shared__ float tile[32][33];
    const int n0 = blockIdx.x * 32;
    const int c0 = blockIdx.y * 32;
    const int b  = blockIdx.z;
    const float* xb = x + (size_t)b * CH * NPIX;
    bf16* hb = hnT + (size_t)b * NPIX * CH;

    #pragma unroll
    for (int r = 0; r < 4; r++) {
        int idx = r * 256 + threadIdx.x;
        int ci = idx >> 5, nj = idx & 31;
        int c = c0 + ci;
        int g = c >> 4;
        float mean = stats[(b * NGRP + g) * 2 + 0];
        float rstd = stats[(b * NGRP + g) * 2 + 1];
        float v = xb[(size_t)c * NPIX + n0 + nj];
        tile[ci][nj] = (v - mean) * rstd * scale[c] + bias[c];
    }
    __syncthreads();
    #pragma unroll
    for (int r = 0; r < 2; r++) {
        int idx = r * 256 + threadIdx.x;
        int ni = idx >> 4, cj = (idx & 15) * 2;
        __nv_bfloat162 w;
        w.x = __float2bfloat16_rn(tile[cj][ni]);
        w.y = __float2bfloat16_rn(tile[cj + 1][ni]);
        *(__nv_bfloat162*)&hb[(size_t)(n0 + ni) * CH + c0 + cj] = w;
    }
}

// ---------------------------------------------------------------------------
// bf16 HMMA GEMM. BM=128, BN template (64|128), BK=32, 8 warps (4 x 2),
// warp tile 32 x (BN/2). 4-stage cp.async, ONE __syncthreads per k-tile.
// Smem rows 40 bf16 (80B) -> ldmatrix conflict-free.
// BIAS_MODE: 0 none, 1 bias[m], 2 bias[n].  OUT_BF: bf16 vs fp32 out.
// ---------------------------------------------------------------------------
template <int BN, int BIAS_MODE, bool RES, bool OUT_BF, int OCC>
__global__ void __launch_bounds__(256, OCC)
hgemm(int K,
      const bf16* __restrict__ A, int lda, size_t sA,
      const bf16* __restrict__ B, int ldb, size_t sB,
      void* __restrict__ Cvp, int ldc, size_t sC,
      const float* __restrict__ bias,
      const float* __restrict__ res, size_t sR,
      float alpha)
{
    constexpr int ROWE   = 40;                 // smem row stride (bf16 elems)
    constexpr int ASZ    = 128 * ROWE;         // 5120
    constexpr int BSZE   = BN * ROWE;
    constexpr int STAGEE = ASZ + BSZE;
    constexpr int NFRAG  = BN / 16;            // n-frags per warp (8 cols each)
    constexpr int NLDSB  = NFRAG / 2;          // ldmatrix.x4 count for B

    extern __shared__ bf16 smem[];
    const int bz = blockIdx.z;
    A += sA * bz;
    B += sB * bz;
    if (RES) res += sR * bz;

    const int m0 = blockIdx.y * 128;
    const int n0 = blockIdx.x * BN;
    const int tid  = threadIdx.x;
    const int lane = tid & 31;
    const int wid  = tid >> 5;
    const int wm   = wid >> 1;
    const int wn   = wid & 1;
    const int grp  = lane >> 2;
    const int tig  = lane & 3;
    const int lrow = lane & 15;
    const int lkof = (lane >> 4) << 3;

    float acc[2][NFRAG][4];
    #pragma unroll
    for (int mi = 0; mi < 2; mi++)
        #pragma unroll
        for (int ni = 0; ni < NFRAG; ni++)
            #pragma unroll
            for (int r = 0; r < 4; r++)
                acc[mi][ni][r] = 0.f;

    auto load_tile = [&](int k0, int st) {
        bf16* As = smem + st * STAGEE;
        bf16* Bs = As + ASZ;
        #pragma unroll
        for (int r = 0; r < 2; r++) {
            int idx = r * 256 + tid;
            int row = idx >> 2, c = idx & 3;
            cp16(&As[row * ROWE + c * 8], A + (size_t)(m0 + row) * lda + k0 + c * 8);
        }
        #pragma unroll
        for (int r = 0; r < BN / 64; r++) {
            int idx = r * 256 + tid;
            int row = idx >> 2, c = idx & 3;
            cp16(&Bs[row * ROWE + c * 8], B + (size_t)(n0 + row) * ldb + k0 + c * 8);
        }
    };

    const int nt = K / 32;
    load_tile(0, 0);  cp_commit();
    load_tile(32, 1); cp_commit();
    load_tile(64, 2); cp_commit();

    for (int t = 0; t < nt; t++) {
        cp_wait2();
        __syncthreads();
        const int st = t & 3;
        if (t + 3 < nt) load_tile((t + 3) * 32, (t + 3) & 3);
        cp_commit();

        const bf16* As = smem + st * STAGEE;
        const bf16* Bs = As + ASZ;

        #pragma unroll
        for (int ks = 0; ks < 32; ks += 16) {
            uint32_t af[2][4];
            #pragma unroll
            for (int mi = 0; mi < 2; mi++) {
                int row = wm * 32 + mi * 16 + lrow;
                uint32_t a = smem_u32(&As[row * ROWE + ks + lkof]);
                ldsm_x4(af[mi][0], af[mi][1], af[mi][2], af[mi][3], a);
            }
            uint32_t bfr[NFRAG][2];
            #pragma unroll
            for (int nb = 0; nb < NLDSB; nb++) {
                int row = wn * (BN / 2) + nb * 16 + lrow;
                uint32_t a = smem_u32(&Bs[row * ROWE + ks + lkof]);
                uint32_t r0, r1, r2, r3;
                ldsm_x4(r0, r1, r2, r3, a);
                bfr[nb * 2][0] = r0; bfr[nb * 2][1] = r2;
                bfr[nb * 2 + 1][0] = r1; bfr[nb * 2 + 1][1] = r3;
            }
            #pragma unroll
            for (int mi = 0; mi < 2; mi++)
                #pragma unroll
                for (int ni = 0; ni < NFRAG; ni++)
                    mma_bf16(acc[mi][ni], af[mi], bfr[ni]);
        }
    }

    #pragma unroll
    for (int mi = 0; mi < 2; mi++) {
        int r0 = m0 + wm * 32 + mi * 16 + grp;
        int r1 = r0 + 8;
        float brow0 = (BIAS_MODE == 1) ? bias[r0] : 0.f;
        float brow1 = (BIAS_MODE == 1) ? bias[r1] : 0.f;
        #pragma unroll
        for (int ni = 0; ni < NFRAG; ni++) {
            int c = n0 + wn * (BN / 2) + ni * 8 + tig * 2;
            float v0 = acc[mi][ni][0] * alpha;
            float v1 = acc[mi][ni][1] * alpha;
            float v2 = acc[mi][ni][2] * alpha;
            float v3 = acc[mi][ni][3] * alpha;
            if (BIAS_MODE == 1) { v0 += brow0; v1 += brow0; v2 += brow1; v3 += brow1; }
            if (BIAS_MODE == 2) {
                float bc0 = bias[c], bc1 = bias[c + 1];
                v0 += bc0; v1 += bc1; v2 += bc0; v3 += bc1;
            }
            if (RES) {
                v0 += res[(size_t)r0 * ldc + c];
                v1 += res[(size_t)r0 * ldc + c + 1];
                v2 += res[(size_t)r1 * ldc + c];
                v3 += res[(size_t)r1 * ldc + c + 1];
            }
            if (OUT_BF) {
                bf16* Cp = (bf16*)Cvp + sC * bz;
                __nv_bfloat162 w0, w1;
                w0.x = __float2bfloat16_rn(v0); w0.y = __float2bfloat16_rn(v1);
                w1.x = __float2bfloat16_rn(v2); w1.y = __float2bfloat16_rn(v3);
                *(__nv_bfloat162*)&Cp[(size_t)r0 * ldc + c] = w0;
                *(__nv_bfloat162*)&Cp[(size_t)r1 * ldc + c] = w1;
            } else {
                float* Cp = (float*)Cvp + sC * bz;
                *(float2*)&Cp[(size_t)r0 * ldc + c] = make_float2(v0, v1);
                *(float2*)&Cp[(size_t)r1 * ldc + c] = make_float2(v2, v3);
            }
        }
    }
}

// ---------------------------------------------------------------------------
// Row softmax: fp32 logits -> bf16 probs
// ---------------------------------------------------------------------------
__global__ void __launch_bounds__(256)
softmax_kernel(const float* __restrict__ attn, bf16* __restrict__ probs)
{
    const float4* p = (const float4*)(attn + (size_t)blockIdx.x * NPIX);
    bf16* po = probs + (size_t)blockIdx.x * NPIX;
    const int tid = threadIdx.x;
    float4 lv[4];
    float mx = -1e30f;
    #pragma unroll
    for (int j = 0; j < 4; j++) {
        lv[j] = p[j * 256 + tid];
        mx = fmaxf(fmaxf(fmaxf(mx, lv[j].x), fmaxf(lv[j].y, lv[j].z)), lv[j].w);
    }
    __shared__ float sh[8];
    #pragma unroll
    for (int o = 16; o; o >>= 1) mx = fmaxf(mx, __shfl_xor_sync(0xffffffffu, mx, o));
    if ((tid & 31) == 0) sh[tid >> 5] = mx;
    __syncthreads();
    if (tid < 32) {
        float v = (tid < 8) ? sh[tid] : -1e30f;
        #pragma unroll
        for (int o = 4; o; o >>= 1) v = fmaxf(v, __shfl_xor_sync(0xffffffffu, v, o));
        if (tid == 0) sh[0] = v;
    }
    __syncthreads();
    mx = sh[0];
    __syncthreads();

    float s = 0.f;
    #pragma unroll
    for (int j = 0; j < 4; j++) {
        lv[j].x = __expf(lv[j].x - mx); lv[j].y = __expf(lv[j].y - mx);
        lv[j].z = __expf(lv[j].z - mx); lv[j].w = __expf(lv[j].w - mx);
        s += lv[j].x + lv[j].y + lv[j].z + lv[j].w;
    }
    #pragma unroll
    for (int o = 16; o; o >>= 1) s += __shfl_xor_sync(0xffffffffu, s, o);
    if ((tid & 31) == 0) sh[tid >> 5] = s;
    __syncthreads();
    if (tid < 32) {
        float v = (tid < 8) ? sh[tid] : 0.f;
        #pragma unroll
        for (int o = 4; o; o >>= 1) v += __shfl_xor_sync(0xffffffffu, v, o);
        if (tid == 0) sh[0] = v;
    }
    __syncthreads();
    float inv = 1.f / sh[0];
    #pragma unroll
    for (int j = 0; j < 4; j++) {
        __nv_bfloat162 w0, w1;
        w0.x = __float2bfloat16_rn(lv[j].x * inv);
        w0.y = __float2bfloat16_rn(lv[j].y * inv);
        w1.x = __float2bfloat16_rn(lv[j].z * inv);
        w1.y = __float2bfloat16_rn(lv[j].w * inv);
        *(__nv_bfloat162*)&po[(j * 256 + tid) * 4]     = w0;
        *(__nv_bfloat162*)&po[(j * 256 + tid) * 4 + 2] = w1;
    }
}

// ---------------------------------------------------------------------------
// Launch
// ---------------------------------------------------------------------------
static constexpr int SMEM64  = 4 * (128 * 40 + 64 * 40) * 2;    // 61440
static constexpr int SMEM128 = 4 * (128 * 40 + 128 * 40) * 2;   // 81920

extern "C" void kernel_launch(void* const* d_in, const int* in_sizes, int n_in,
                              void* d_out, int out_size)
{
    const float* x        = (const float*)d_in[0];
    const float* gn_scale = (const float*)d_in[1];
    const float* gn_bias  = (const float*)d_in[2];
    const float* wq       = (const float*)d_in[3];
    const float* bq       = (const float*)d_in[4];
    const float* wk       = (const float*)d_in[5];
    const float* bk       = (const float*)d_in[6];
    const float* wv       = (const float*)d_in[7];
    const float* bv       = (const float*)d_in[8];
    const float* wp       = (const float*)d_in[9];
    const float* bp       = (const float*)d_in[10];
    float* out            = (float*)d_out;

    static bf16 *hnT = nullptr, *qkT, *v, *probs, *oT, *rwqk, *rwv, *rwp;
    static float *attn, *stats, *bqk;
    if (!hnT) {
        cudaGetSymbolAddress((void**)&hnT,  g_hn);
        cudaGetSymbolAddress((void**)&qkT,  g_qk);
        cudaGetSymbolAddress((void**)&v,    g_v);
        cudaGetSymbolAddress((void**)&probs,g_p);
        cudaGetSymbolAddress((void**)&oT,   g_o);
        cudaGetSymbolAddress((void**)&attn, g_attn);
        cudaGetSymbolAddress((void**)&rwqk, g_wqk);
        cudaGetSymbolAddress((void**)&rwv,  g_wv);
        cudaGetSymbolAddress((void**)&rwp,  g_wp);
        cudaGetSymbolAddress((void**)&bqk,  g_bqk);
        cudaGetSymbolAddress((void**)&stats, g_stats);
        cudaFuncSetAttribute(hgemm<64, 2, false, true,  3>,
                             cudaFuncAttributeMaxDynamicSharedMemorySize, SMEM64);
        cudaFuncSetAttribute(hgemm<64, 1, false, true,  3>,
                             cudaFuncAttributeMaxDynamicSharedMemorySize, SMEM64);
        cudaFuncSetAttribute(hgemm<128, 0, false, false, 2>,
                             cudaFuncAttributeMaxDynamicSharedMemorySize, SMEM128);
        cudaFuncSetAttribute(hgemm<64, 0, false, true,  3>,
                             cudaFuncAttributeMaxDynamicSharedMemorySize, SMEM64);
        cudaFuncSetAttribute(hgemm<64, 1, true,  false, 3>,
                             cudaFuncAttributeMaxDynamicSharedMemorySize, SMEM64);
    }

    const size_t sCN = (size_t)CH * NPIX;
    const size_t sNN = (size_t)NPIX * NPIX;
    const size_t sQK = (size_t)NPIX * 2 * CH;
    const float inv_sqrt_c = 0.044194173824159216f;   // 1/sqrt(512)

    round_weights_kernel<<<4 * CH * CH / 256, 256>>>(wq, wk, wv, wp, rwqk, rwv, rwp);
    bias_concat_kernel<<<4, 256>>>(bq, bk, bqk);
    gn_stats_kernel<<<BSZ * NGRP, 256>>>(x, stats);
    gn_transpose_kernel<<<dim3(NPIX / 32, CH / 32, BSZ), 256>>>(x, stats, gn_scale, gn_bias, hnT);

    // qkT[n, 0:1024] = hnT[n,:] . Wqk[d,:]^T + bqk   (M=4096, N=1024, K=512)
    hgemm<64, 2, false, true, 3><<<dim3(2 * CH / 64, NPIX / 128, BSZ), 256, SMEM64>>>(
        CH, hnT, CH, sCN, rwqk, CH, 0, qkT, 2 * CH, sQK, bqk, nullptr, 0, 1.f);

    // v[d,n] = Wv[d,:] . hnT[n,:]^T + bv[d]   (M=512, N=4096, K=512)
    hgemm<64, 1, false, true, 3><<<dim3(NPIX / 64, CH / 128, BSZ), 256, SMEM64>>>(
        CH, rwv, CH, 0, hnT, CH, sCN, v, NPIX, sCN, bv, nullptr, 0, 1.f);

    // logits[i,j] = alpha * qT[i,:] . kT[j,:]   (M=N=4096, K=512)
    hgemm<128, 0, false, false, 2><<<dim3(NPIX / 128, NPIX / 128, BSZ), 256, SMEM128>>>(
        CH, qkT, 2 * CH, sQK, qkT + CH, 2 * CH, sQK, attn, NPIX, sNN,
        nullptr, nullptr, 0, inv_sqrt_c);

    softmax_kernel<<<BSZ * NPIX, 256>>>(attn, probs);

    // oT[i,c] = probs[i,:] . v[c,:]   (M=4096, N=512, K=4096)
    hgemm<64, 0, false, true, 3><<<dim3(CH / 64, NPIX / 128, BSZ), 256, SMEM64>>>(
        NPIX, probs, NPIX, sNN, v, NPIX, sCN, oT, CH, sCN, nullptr, nullptr, 0, 1.f);

    // out[d,n] = Wp[d,:] . oT[n,:]^T + bp[d] + x[d,n]   (M=512, N=4096, K=512)
    hgemm<64, 1, true, false, 3><<<dim3(NPIX / 64, CH / 128, BSZ), 256, SMEM64>>>(
        CH, rwp, CH, 0, oT, CH, sCN, out, NPIX, sCN, bp, x, sCN, 1.f);
}

// round 11
// speedup vs baseline: 5.8516x; 1.0429x over previous
#include <cuda_runtime.h>
#include <cuda_bf16.h>
#include <math.h>
#include <stdint.h>

// ---------------------------------------------------------------------------
// AttentionBlock, legacy-HMMA bf16 (tcgen05 unavailable on this toolchain).
// R11: softmax fused into QK epilogue (exp + deterministic row-sum partials),
// AV epilogue applies 1/rowsum. No fp32 logits buffer, no softmax kernel.
// D[M,N] = alpha * A[M,K] . B[N,K]^T, bf16 in, fp32 accum.
// ---------------------------------------------------------------------------

static constexpr int BSZ  = 2;
static constexpr int CH   = 512;
static constexpr int NPIX = 4096;
static constexpr int NGRP = 32;
static constexpr int JT   = NPIX / 128;   // 32 j-tiles per row

typedef __nv_bfloat16 bf16;

__device__ bf16  g_hn[(size_t)BSZ * CH * NPIX];          // hnT [b][n][c]
__device__ bf16  g_qk[(size_t)BSZ * NPIX * 2 * CH];      // qkT [b][n][1024]
__device__ bf16  g_v [(size_t)BSZ * CH * NPIX];          // v   [b][c][n]
__device__ bf16  g_o [(size_t)BSZ * CH * NPIX];          // oT  [b][n][c]
__device__ bf16  g_p [(size_t)BSZ * NPIX * NPIX];        // p~ = exp(logit) bf16
__device__ float g_psum[(size_t)BSZ * NPIX * JT];        // per-tile row sums
__device__ float g_inv [(size_t)BSZ * NPIX];             // 1/rowsum
__device__ bf16  g_wqk[2 * CH * CH];
__device__ bf16  g_wv[CH * CH];
__device__ bf16  g_wp[CH * CH];
__device__ float g_bqk[2 * CH];
__device__ float g_stats[BSZ * NGRP * 2];

// ---------------------------------------------------------------------------
__device__ __forceinline__ uint32_t smem_u32(const void* p) {
    return (uint32_t)__cvta_generic_to_shared(p);
}
__device__ __forceinline__ void cp16(void* dst, const void* src) {
    asm volatile("cp.async.cg.shared.global [%0], [%1], 16;"
                 :: "r"(smem_u32(dst)), "l"(src));
}
__device__ __forceinline__ void cp_commit() { asm volatile("cp.async.commit_group;"); }
__device__ __forceinline__ void cp_wait2()  { asm volatile("cp.async.wait_group 2;"); }

__device__ __forceinline__ void ldsm_x4(uint32_t& r0, uint32_t& r1,
                                        uint32_t& r2, uint32_t& r3, uint32_t a) {
    asm volatile("ldmatrix.sync.aligned.m8n8.x4.shared.b16 {%0,%1,%2,%3}, [%4];"
                 : "=r"(r0), "=r"(r1), "=r"(r2), "=r"(r3) : "r"(a));
}
__device__ __forceinline__ void mma_bf16(float* c, const uint32_t* a, const uint32_t* b) {
    asm volatile(
        "mma.sync.aligned.m16n8k16.row.col.f32.bf16.bf16.f32 "
        "{%0,%1,%2,%3}, {%4,%5,%6,%7}, {%8,%9}, {%0,%1,%2,%3};"
        : "+f"(c[0]), "+f"(c[1]), "+f"(c[2]), "+f"(c[3])
        : "r"(a[0]), "r"(a[1]), "r"(a[2]), "r"(a[3]), "r"(b[0]), "r"(b[1]));
}

// ---------------------------------------------------------------------------
// prep
// ---------------------------------------------------------------------------
__global__ void round_weights_kernel(const float* __restrict__ a, const float* __restrict__ b,
                                     const float* __restrict__ c, const float* __restrict__ d,
                                     bf16* __restrict__ wqk, bf16* __restrict__ wv,
                                     bf16* __restrict__ wp)
{
    int i = blockIdx.x * blockDim.x + threadIdx.x;
    int w = i >> 18;
    int off = i & ((1 << 18) - 1);
    const float* src = (w == 0) ? a : (w == 1) ? b : (w == 2) ? c : d;
    bf16* dst = (w == 0) ? wqk : (w == 1) ? (wqk + CH * CH) : (w == 2) ? wv : wp;
    dst[off] = __float2bfloat16_rn(src[off]);
}
__global__ void bias_concat_kernel(const float* __restrict__ bq,
                                   const float* __restrict__ bk,
                                   float* __restrict__ o)
{
    int i = blockIdx.x * blockDim.x + threadIdx.x;
    o[i] = (i < CH) ? bq[i] : bk[i - CH];
}

// ---------------------------------------------------------------------------
// GroupNorm stats
// ---------------------------------------------------------------------------
__global__ void gn_stats_kernel(const float* __restrict__ x, float* __restrict__ stats)
{
    const int NPG = (CH / NGRP) * NPIX;
    const float* xp = x + (size_t)blockIdx.x * NPG;
    float s = 0.f, ss = 0.f;
    for (int i = threadIdx.x; i < NPG; i += blockDim.x) {
        float v = xp[i];
        s += v; ss += v * v;
    }
    __shared__ float sh[64];
    #pragma unroll
    for (int o = 16; o; o >>= 1) {
        s  += __shfl_xor_sync(0xffffffffu, s,  o);
        ss += __shfl_xor_sync(0xffffffffu, ss, o);
    }
    int wid = threadIdx.x >> 5, lid = threadIdx.x & 31;
    if (lid == 0) { sh[wid] = s; sh[32 + wid] = ss; }
    __syncthreads();
    if (threadIdx.x < 32) {
        s  = (lid < 8) ? sh[lid]      : 0.f;
        ss = (lid < 8) ? sh[32 + lid] : 0.f;
        #pragma unroll
        for (int o = 4; o; o >>= 1) {
            s  += __shfl_xor_sync(0xffffffffu, s,  o);
            ss += __shfl_xor_sync(0xffffffffu, ss, o);
        }
        if (lid == 0) {
            float mean = s / (float)NPG;
            float var  = ss / (float)NPG - mean * mean;
            stats[blockIdx.x * 2 + 0] = mean;
            stats[blockIdx.x * 2 + 1] = rsqrtf(var + 1e-6f);
        }
    }
}

// ---------------------------------------------------------------------------
// Normalize + transpose: x[b][c][n] -> hnT[b][n][c] bf16
// ---------------------------------------------------------------------------
__global__ void __launch_bounds__(256)
gn_transpose_kernel(const float* __restrict__ x, const float* __restrict__ stats,
                    const float* __restrict__ scale, const float* __restrict__ bias,
                    bf16* __restrict__ hnT)
{
    __shared__ float tile[32][33];
    const int n0 = blockIdx.x * 32;
    const int c0 = blockIdx.y * 32;
    const int b  = blockIdx.z;
    const float* xb = x + (size_t)b * CH * NPIX;
    bf16* hb = hnT + (size_t)b * NPIX * CH;

    #pragma unroll
    for (int r = 0; r < 4; r++) {
        int idx = r * 256 + threadIdx.x;
        int ci = idx >> 5, nj = idx & 31;
        int c = c0 + ci;
        int g = c >> 4;
        float mean = stats[(b * NGRP + g) * 2 + 0];
        float rstd = stats[(b * NGRP + g) * 2 + 1];
        float v = xb[(size_t)c * NPIX + n0 + nj];
        tile[ci][nj] = (v - mean) * rstd * scale[c] + bias[c];
    }
    __syncthreads();
    #pragma unroll
    for (int r = 0; r < 2; r++) {
        int idx = r * 256 + threadIdx.x;
        int ni = idx >> 4, cj = (idx & 15) * 2;
        __nv_bfloat162 w;
        w.x = __float2bfloat16_rn(tile[cj][ni]);
        w.y = __float2bfloat16_rn(tile[cj + 1][ni]);
        *(__nv_bfloat162*)&hb[(size_t)(n0 + ni) * CH + c0 + cj] = w;
    }
}

// ---------------------------------------------------------------------------
// rowsum reduce: inv[i] = 1 / sum_j psum[i][j]  (fixed order, deterministic)
// ---------------------------------------------------------------------------
__global__ void rowsum_inv_kernel(const float* __restrict__ psum, float* __restrict__ inv)
{
    int i = blockIdx.x * blockDim.x + threadIdx.x;   // 0 .. BSZ*NPIX-1
    const float* p = psum + (size_t)i * JT;
    float s = 0.f;
    #pragma unroll
    for (int j = 0; j < JT; j++) s += p[j];
    inv[i] = 1.f / s;
}

// ---------------------------------------------------------------------------
// bf16 HMMA GEMM. BM=128, BN template, BK=32, 8 warps (4x2),
// 4-stage cp.async, one __syncthreads per k-tile. smem rows 40 bf16 (80B).
// BIAS_MODE: 0 none, 1 bias[m], 2 bias[n],
//            3 softmax epilogue (p~=exp(alpha*acc) bf16 + row-partials into
//              (float*)bias, batch stride NPIX*JT),
//            4 row-scale epilogue (v *= bias[b*NPIX + m]).
// ---------------------------------------------------------------------------
template <int BN, int BIAS_MODE, bool RES, bool OUT_BF, int OCC>
__global__ void __launch_bounds__(256, OCC)
hgemm(int K,
      const bf16* __restrict__ A, int lda, size_t sA,
      const bf16* __restrict__ B, int ldb, size_t sB,
      void* __restrict__ Cvp, int ldc, size_t sC,
      const float* __restrict__ bias,
      const float* __restrict__ res, size_t sR,
      float alpha)
{
    constexpr int ROWE   = 40;
    constexpr int ASZ    = 128 * ROWE;
    constexpr int BSZE   = BN * ROWE;
    constexpr int STAGEE = ASZ + BSZE;
    constexpr int NFRAG  = BN / 16;
    constexpr int NLDSB  = NFRAG / 2;

    extern __shared__ bf16 smem[];
    const int bz = blockIdx.z;
    A += sA * bz;
    B += sB * bz;
    if (RES) res += sR * bz;

    const int m0 = blockIdx.y * 128;
    const int n0 = blockIdx.x * BN;
    const int tid  = threadIdx.x;
    const int lane = tid & 31;
    const int wid  = tid >> 5;
    const int wm   = wid >> 1;
    const int wn   = wid & 1;
    const int grp  = lane >> 2;
    const int tig  = lane & 3;
    const int lrow = lane & 15;
    const int lkof = (lane >> 4) << 3;

    float acc[2][NFRAG][4];
    #pragma unroll
    for (int mi = 0; mi < 2; mi++)
        #pragma unroll
        for (int ni = 0; ni < NFRAG; ni++)
            #pragma unroll
            for (int r = 0; r < 4; r++)
                acc[mi][ni][r] = 0.f;

    auto load_tile = [&](int k0, int st) {
        bf16* As = smem + st * STAGEE;
        bf16* Bs = As + ASZ;
        #pragma unroll
        for (int r = 0; r < 2; r++) {
            int idx = r * 256 + tid;
            int row = idx >> 2, c = idx & 3;
            cp16(&As[row * ROWE + c * 8], A + (size_t)(m0 + row) * lda + k0 + c * 8);
        }
        #pragma unroll
        for (int r = 0; r < BN / 64; r++) {
            int idx = r * 256 + tid;
            int row = idx >> 2, c = idx & 3;
            cp16(&Bs[row * ROWE + c * 8], B + (size_t)(n0 + row) * ldb + k0 + c * 8);
        }
    };

    const int nt = K / 32;
    load_tile(0, 0);  cp_commit();
    load_tile(32, 1); cp_commit();
    load_tile(64, 2); cp_commit();

    for (int t = 0; t < nt; t++) {
        cp_wait2();
        __syncthreads();
        const int st = t & 3;
        if (t + 3 < nt) load_tile((t + 3) * 32, (t + 3) & 3);
        cp_commit();

        const bf16* As = smem + st * STAGEE;
        const bf16* Bs = As + ASZ;

        #pragma unroll
        for (int ks = 0; ks < 32; ks += 16) {
            uint32_t af[2][4];
            #pragma unroll
            for (int mi = 0; mi < 2; mi++) {
                int row = wm * 32 + mi * 16 + lrow;
                uint32_t a = smem_u32(&As[row * ROWE + ks + lkof]);
                ldsm_x4(af[mi][0], af[mi][1], af[mi][2], af[mi][3], a);
            }
            uint32_t bfr[NFRAG][2];
            #pragma unroll
            for (int nb = 0; nb < NLDSB; nb++) {
                int row = wn * (BN / 2) + nb * 16 + lrow;
                uint32_t a = smem_u32(&Bs[row * ROWE + ks + lkof]);
                uint32_t r0, r1, r2, r3;
                ldsm_x4(r0, r1, r2, r3, a);
                bfr[nb * 2][0] = r0; bfr[nb * 2][1] = r2;
                bfr[nb * 2 + 1][0] = r1; bfr[nb * 2 + 1][1] = r3;
            }
            #pragma unroll
            for (int mi = 0; mi < 2; mi++)
                #pragma unroll
                for (int ni = 0; ni < NFRAG; ni++)
                    mma_bf16(acc[mi][ni], af[mi], bfr[ni]);
        }
    }

    // -------------------- epilogue --------------------
    float* rows_s = (float*)smem;   // softmax partials; smem dead after loop
    if (BIAS_MODE == 3) {
        __syncthreads();
        if (tid < 128) rows_s[tid] = 0.f;
        __syncthreads();
    }

    #pragma unroll
    for (int mi = 0; mi < 2; mi++) {
        int lr0 = wm * 32 + mi * 16 + grp;
        int r0 = m0 + lr0;
        int r1 = r0 + 8;
        float brow0 = (BIAS_MODE == 1) ? bias[r0] : 0.f;
        float brow1 = (BIAS_MODE == 1) ? bias[r1] : 0.f;
        float sc0 = 1.f, sc1 = 1.f;
        if (BIAS_MODE == 4) {
            sc0 = bias[(size_t)bz * NPIX + r0];
            sc1 = bias[(size_t)bz * NPIX + r1];
        }
        float rsum0 = 0.f, rsum1 = 0.f;
        #pragma unroll
        for (int ni = 0; ni < NFRAG; ni++) {
            int c = n0 + wn * (BN / 2) + ni * 8 + tig * 2;
            float v0 = acc[mi][ni][0] * alpha;
            float v1 = acc[mi][ni][1] * alpha;
            float v2 = acc[mi][ni][2] * alpha;
            float v3 = acc[mi][ni][3] * alpha;
            if (BIAS_MODE == 1) { v0 += brow0; v1 += brow0; v2 += brow1; v3 += brow1; }
            if (BIAS_MODE == 2) {
                float bc0 = bias[c], bc1 = bias[c + 1];
                v0 += bc0; v1 += bc1; v2 += bc0; v3 += bc1;
            }
            if (BIAS_MODE == 3) {
                v0 = __expf(v0); v1 = __expf(v1);
                v2 = __expf(v2); v3 = __expf(v3);
                rsum0 += v0 + v1; rsum1 += v2 + v3;
            }
            if (BIAS_MODE == 4) { v0 *= sc0; v1 *= sc0; v2 *= sc1; v3 *= sc1; }
            if (RES) {
                v0 += res[(size_t)r0 * ldc + c];
                v1 += res[(size_t)r0 * ldc + c + 1];
                v2 += res[(size_t)r1 * ldc + c];
                v3 += res[(size_t)r1 * ldc + c + 1];
            }
            if (OUT_BF) {
                bf16* Cp = (bf16*)Cvp + sC * bz;
                __nv_bfloat162 w0, w1;
                w0.x = __float2bfloat16_rn(v0); w0.y = __float2bfloat16_rn(v1);
                w1.x = __float2bfloat16_rn(v2); w1.y = __float2bfloat16_rn(v3);
                *(__nv_bfloat162*)&Cp[(size_t)r0 * ldc + c] = w0;
                *(__nv_bfloat162*)&Cp[(size_t)r1 * ldc + c] = w1;
            } else {
                float* Cp = (float*)Cvp + sC * bz;
                *(float2*)&Cp[(size_t)r0 * ldc + c] = make_float2(v0, v1);
                *(float2*)&Cp[(size_t)r1 * ldc + c] = make_float2(v2, v3);
            }
        }
        if (BIAS_MODE == 3) {
            // reduce over the 4 tig lanes (adjacent); then 2 warps (wn) add
            rsum0 += __shfl_xor_sync(0xffffffffu, rsum0, 1);
            rsum0 += __shfl_xor_sync(0xffffffffu, rsum0, 2);
            rsum1 += __shfl_xor_sync(0xffffffffu, rsum1, 1);
            rsum1 += __shfl_xor_sync(0xffffffffu, rsum1, 2);
            if (tig == 0) {
                atomicAdd(&rows_s[lr0], rsum0);       // 2 commutative adds/row
                atomicAdd(&rows_s[lr0 + 8], rsum1);   // -> deterministic
            }
        }
    }
    if (BIAS_MODE == 3) {
        __syncthreads();
        if (tid < 128) {
            float* psum = (float*)bias;
            psum[((size_t)bz * NPIX + m0 + tid) * JT + blockIdx.x] = rows_s[tid];
        }
    }
}

// ---------------------------------------------------------------------------
// Launch
// ---------------------------------------------------------------------------
static constexpr int SMEM64  = 4 * (128 * 40 + 64 * 40) * 2;    // 61440
static constexpr int SMEM128 = 4 * (128 * 40 + 128 * 40) * 2;   // 81920

extern "C" void kernel_launch(void* const* d_in, const int* in_sizes, int n_in,
                              void* d_out, int out_size)
{
    const float* x        = (const float*)d_in[0];
    const float* gn_scale = (const float*)d_in[1];
    const float* gn_bias  = (const float*)d_in[2];
    const float* wq       = (const float*)d_in[3];
    const float* bq       = (const float*)d_in[4];
    const float* wk       = (const float*)d_in[5];
    const float* bk       = (const float*)d_in[6];
    const float* wv       = (const float*)d_in[7];
    const float* bv       = (const float*)d_in[8];
    const float* wp       = (const float*)d_in[9];
    const float* bp       = (const float*)d_in[10];
    float* out            = (float*)d_out;

    static bf16 *hnT = nullptr, *qkT, *v, *probs, *oT, *rwqk, *rwv, *rwp;
    static float *stats, *bqk, *psum, *inv;
    if (!hnT) {
        cudaGetSymbolAddress((void**)&hnT,  g_hn);
        cudaGetSymbolAddress((void**)&qkT,  g_qk);
        cudaGetSymbolAddress((void**)&v,    g_v);
        cudaGetSymbolAddress((void**)&probs,g_p);
        cudaGetSymbolAddress((void**)&oT,   g_o);
        cudaGetSymbolAddress((void**)&rwqk, g_wqk);
        cudaGetSymbolAddress((void**)&rwv,  g_wv);
        cudaGetSymbolAddress((void**)&rwp,  g_wp);
        cudaGetSymbolAddress((void**)&bqk,  g_bqk);
        cudaGetSymbolAddress((void**)&stats, g_stats);
        cudaGetSymbolAddress((void**)&psum, g_psum);
        cudaGetSymbolAddress((void**)&inv,  g_inv);
        cudaFuncSetAttribute(hgemm<64, 2, false, true,  3>,
                             cudaFuncAttributeMaxDynamicSharedMemorySize, SMEM64);
        cudaFuncSetAttribute(hgemm<64, 1, false, true,  3>,
                             cudaFuncAttributeMaxDynamicSharedMemorySize, SMEM64);
        cudaFuncSetAttribute(hgemm<128, 3, false, true, 2>,
                             cudaFuncAttributeMaxDynamicSharedMemorySize, SMEM128);
        cudaFuncSetAttribute(hgemm<64, 4, false, true,  3>,
                             cudaFuncAttributeMaxDynamicSharedMemorySize, SMEM64);
        cudaFuncSetAttribute(hgemm<64, 1, true,  false, 3>,
                             cudaFuncAttributeMaxDynamicSharedMemorySize, SMEM64);
    }

    const size_t sCN = (size_t)CH * NPIX;
    const size_t sNN = (size_t)NPIX * NPIX;
    const size_t sQK = (size_t)NPIX * 2 * CH;
    const float inv_sqrt_c = 0.044194173824159216f;   // 1/sqrt(512)

    round_weights_kernel<<<4 * CH * CH / 256, 256>>>(wq, wk, wv, wp, rwqk, rwv, rwp);
    bias_concat_kernel<<<4, 256>>>(bq, bk, bqk);
    gn_stats_kernel<<<BSZ * NGRP, 256>>>(x, stats);
    gn_transpose_kernel<<<dim3(NPIX / 32, CH / 32, BSZ), 256>>>(x, stats, gn_scale, gn_bias, hnT);

    // qkT[n, 0:1024] = hnT[n,:] . Wqk^T + bqk   (M=4096, N=1024, K=512)
    hgemm<64, 2, false, true, 3><<<dim3(2 * CH / 64, NPIX / 128, BSZ), 256, SMEM64>>>(
        CH, hnT, CH, sCN, rwqk, CH, 0, qkT, 2 * CH, sQK, bqk, nullptr, 0, 1.f);

    // v[d,n] = Wv . hnT^T + bv[d]   (M=512, N=4096, K=512)
    hgemm<64, 1, false, true, 3><<<dim3(NPIX / 64, CH / 128, BSZ), 256, SMEM64>>>(
        CH, rwv, CH, 0, hnT, CH, sCN, v, NPIX, sCN, bv, nullptr, 0, 1.f);

    // p~[i,j] = exp(alpha * qT[i,:] . kT[j,:]) bf16 + row partial sums
    hgemm<128, 3, false, true, 2><<<dim3(NPIX / 128, NPIX / 128, BSZ), 256, SMEM128>>>(
        CH, qkT, 2 * CH, sQK, qkT + CH, 2 * CH, sQK, probs, NPIX, sNN,
        psum, nullptr, 0, inv_sqrt_c);

    // inv[i] = 1 / rowsum_i
    rowsum_inv_kernel<<<BSZ * NPIX / 256, 256>>>(psum, inv);

    // oT[i,c] = inv[i] * (p~[i,:] . v[c,:])   (M=4096, N=512, K=4096)
    hgemm<64, 4, false, true, 3><<<dim3(CH / 64, NPIX / 128, BSZ), 256, SMEM64>>>(
        NPIX, probs, NPIX, sNN, v, NPIX, sCN, oT, CH, sCN, inv, nullptr, 0, 1.f);

    // out[d,n] = Wp . oT^T + bp[d] + x[d,n]   (M=512, N=4096, K=512)
    hgemm<64, 1, true, false, 3><<<dim3(NPIX / 64, CH / 128, BSZ), 256, SMEM64>>>(
        CH, rwp, CH, 0, oT, CH, sCN, out, NPIX, sCN, bp, x, sCN, 1.f);
}

// round 13
// speedup vs baseline: 7.7760x; 1.3289x over previous
#include <cuda_runtime.h>
#include <cuda.h>
#include <cuda_bf16.h>
#include <math.h>
#include <stdint.h>

// ---------------------------------------------------------------------------
// AttentionBlock, bf16 mma.m16n8k16 + TMA operand loads (sm_103-safe subset).
// R12: replace per-16B cp.async (768 issues/k-tile, LSU-floor-bound) with
// 2 TMA tensor loads per stage. BM=BN=128, BK=64 (SW128), 3 stages.
// D[M,N] = alpha * A[M,K] . B[N,K]^T, bf16 in, fp32 accum.
// ---------------------------------------------------------------------------

static constexpr int BSZ  = 2;
static constexpr int CH   = 512;
static constexpr int NPIX = 4096;
static constexpr int NGRP = 32;
static constexpr int JT   = NPIX / 128;

typedef __nv_bfloat16 bf16;

__device__ bf16  g_hn[(size_t)BSZ * NPIX * CH];          // hnT [b][n][c]
__device__ bf16  g_qk[(size_t)BSZ * NPIX * 2 * CH];      // qkT [b][n][1024]
__device__ bf16  g_v [(size_t)BSZ * CH * NPIX];          // v   [b][c][n]
__device__ bf16  g_o [(size_t)BSZ * NPIX * CH];          // oT  [b][n][c]
__device__ bf16  g_p [(size_t)BSZ * NPIX * NPIX];        // p~ = exp(logit)
__device__ float g_psum[(size_t)BSZ * NPIX * JT];
__device__ float g_inv [(size_t)BSZ * NPIX];
__device__ bf16  g_wqk[2 * CH * CH];
__device__ bf16  g_wv[CH * CH];
__device__ bf16  g_wp[CH * CH];
__device__ float g_bqk[2 * CH];
__device__ float g_stats[BSZ * NGRP * 2];

// ---------------------------------------------------------------------------
__device__ __forceinline__ uint32_t smem_u32(const void* p) {
    return (uint32_t)__cvta_generic_to_shared(p);
}
__device__ __forceinline__ uint32_t swz(uint32_t off) {
    return off ^ ((off >> 3) & 0x70);
}
__device__ __forceinline__ void mbar_init(uint32_t a, uint32_t cnt) {
    asm volatile("mbarrier.init.shared.b64 [%0], %1;" :: "r"(a), "r"(cnt) : "memory");
}
__device__ __forceinline__ void mbar_expect_tx(uint32_t a, uint32_t bytes) {
    asm volatile("mbarrier.arrive.expect_tx.shared.b64 _, [%0], %1;"
                 :: "r"(a), "r"(bytes) : "memory");
}
__device__ __forceinline__ void mbar_wait(uint32_t a, uint32_t parity) {
    asm volatile(
        "{\n\t.reg .pred P;\n\t"
        "W_%=:\n\t"
        "mbarrier.try_wait.parity.acquire.cta.shared::cta.b64 P, [%0], %1, 0x989680;\n\t"
        "@!P bra W_%=;\n\t}"
        :: "r"(a), "r"(parity) : "memory");
}
__device__ __forceinline__ void tma_load3d(uint32_t dst, const CUtensorMap* tm,
                                           int x, int y, int z, uint32_t mbar) {
    asm volatile(
        "cp.async.bulk.tensor.3d.shared::cta.global.tile.mbarrier::complete_tx::bytes "
        "[%0], [%1, {%2, %3, %4}], [%5];"
        :: "r"(dst), "l"(tm), "r"(x), "r"(y), "r"(z), "r"(mbar) : "memory");
}
__device__ __forceinline__ void ldsm_x4(uint32_t& r0, uint32_t& r1,
                                        uint32_t& r2, uint32_t& r3, uint32_t a) {
    asm volatile("ldmatrix.sync.aligned.m8n8.x4.shared.b16 {%0,%1,%2,%3}, [%4];"
                 : "=r"(r0), "=r"(r1), "=r"(r2), "=r"(r3) : "r"(a));
}
__device__ __forceinline__ void mma_bf16(float* c, const uint32_t* a, const uint32_t* b) {
    asm volatile(
        "mma.sync.aligned.m16n8k16.row.col.f32.bf16.bf16.f32 "
        "{%0,%1,%2,%3}, {%4,%5,%6,%7}, {%8,%9}, {%0,%1,%2,%3};"
        : "+f"(c[0]), "+f"(c[1]), "+f"(c[2]), "+f"(c[3])
        : "r"(a[0]), "r"(a[1]), "r"(a[2]), "r"(a[3]), "r"(b[0]), "r"(b[1]));
}

// ---------------------------------------------------------------------------
// prep kernels
// ---------------------------------------------------------------------------
__global__ void round_weights_kernel(const float* __restrict__ a, const float* __restrict__ b,
                                     const float* __restrict__ c, const float* __restrict__ d,
                                     bf16* __restrict__ wqk, bf16* __restrict__ wv,
                                     bf16* __restrict__ wp)
{
    int i = blockIdx.x * blockDim.x + threadIdx.x;
    int w = i >> 18;
    int off = i & ((1 << 18) - 1);
    const float* src = (w == 0) ? a : (w == 1) ? b : (w == 2) ? c : d;
    bf16* dst = (w == 0) ? wqk : (w == 1) ? (wqk + CH * CH) : (w == 2) ? wv : wp;
    dst[off] = __float2bfloat16_rn(src[off]);
}
__global__ void bias_concat_kernel(const float* __restrict__ bq,
                                   const float* __restrict__ bk,
                                   float* __restrict__ o)
{
    int i = blockIdx.x * blockDim.x + threadIdx.x;
    o[i] = (i < CH) ? bq[i] : bk[i - CH];
}

__global__ void gn_stats_kernel(const float* __restrict__ x, float* __restrict__ stats)
{
    const int NPG = (CH / NGRP) * NPIX;
    const float* xp = x + (size_t)blockIdx.x * NPG;
    float s = 0.f, ss = 0.f;
    for (int i = threadIdx.x; i < NPG; i += blockDim.x) {
        float v = xp[i];
        s += v; ss += v * v;
    }
    __shared__ float sh[64];
    #pragma unroll
    for (int o = 16; o; o >>= 1) {
        s  += __shfl_xor_sync(0xffffffffu, s,  o);
        ss += __shfl_xor_sync(0xffffffffu, ss, o);
    }
    int wid = threadIdx.x >> 5, lid = threadIdx.x & 31;
    if (lid == 0) { sh[wid] = s; sh[32 + wid] = ss; }
    __syncthreads();
    if (threadIdx.x < 32) {
        s  = (lid < 8) ? sh[lid]      : 0.f;
        ss = (lid < 8) ? sh[32 + lid] : 0.f;
        #pragma unroll
        for (int o = 4; o; o >>= 1) {
            s  += __shfl_xor_sync(0xffffffffu, s,  o);
            ss += __shfl_xor_sync(0xffffffffu, ss, o);
        }
        if (lid == 0) {
            float mean = s / (float)NPG;
            float var  = ss / (float)NPG - mean * mean;
            stats[blockIdx.x * 2 + 0] = mean;
            stats[blockIdx.x * 2 + 1] = rsqrtf(var + 1e-6f);
        }
    }
}

__global__ void __launch_bounds__(256)
gn_transpose_kernel(const float* __restrict__ x, const float* __restrict__ stats,
                    const float* __restrict__ scale, const float* __restrict__ bias,
                    bf16* __restrict__ hnT)
{
    __shared__ float tile[32][33];
    const int n0 = blockIdx.x * 32;
    const int c0 = blockIdx.y * 32;
    const int b  = blockIdx.z;
    const float* xb = x + (size_t)b * CH * NPIX;
    bf16* hb = hnT + (size_t)b * NPIX * CH;

    #pragma unroll
    for (int r = 0; r < 4; r++) {
        int idx = r * 256 + threadIdx.x;
        int ci = idx >> 5, nj = idx & 31;
        int c = c0 + ci;
        int g = c >> 4;
        float mean = stats[(b * NGRP + g) * 2 + 0];
        float rstd = stats[(b * NGRP + g) * 2 + 1];
        float v = xb[(size_t)c * NPIX + n0 + nj];
        tile[ci][nj] = (v - mean) * rstd * scale[c] + bias[c];
    }
    __syncthreads();
    #pragma unroll
    for (int r = 0; r < 2; r++) {
        int idx = r * 256 + threadIdx.x;
        int ni = idx >> 4, cj = (idx & 15) * 2;
        __nv_bfloat162 w;
        w.x = __float2bfloat16_rn(tile[cj][ni]);
        w.y = __float2bfloat16_rn(tile[cj + 1][ni]);
        *(__nv_bfloat162*)&hb[(size_t)(n0 + ni) * CH + c0 + cj] = w;
    }
}

__global__ void rowsum_inv_kernel(const float* __restrict__ psum, float* __restrict__ inv)
{
    int i = blockIdx.x * blockDim.x + threadIdx.x;
    const float* p = psum + (size_t)i * JT;
    float s = 0.f;
    #pragma unroll
    for (int j = 0; j < JT; j++) s += p[j];
    inv[i] = 1.f / s;
}

// ---------------------------------------------------------------------------
// TMA-fed bf16 GEMM. BM=BN=128, BK=64 (128B SW128 rows), 3 stages,
// 8 warps (4x2), warp tile 32x64, m16n8k16.
// BIAS_MODE: 0 none, 1 bias[m], 2 bias[n], 3 softmax epi (exp + psum),
//            4 rowscale (bias = inv[b*NPIX+m]).  BA/BB: operand batched.
// ---------------------------------------------------------------------------
static constexpr int TILE_B  = 128 * 128;            // 16KB per operand tile
static constexpr int STAGE_B = 2 * TILE_B;           // 32KB
static constexpr int GSMEM   = 1024 + 3 * STAGE_B + 64;   // align pad + mbar

template <int BIAS_MODE, bool RES, bool OUT_BF, bool BA, bool BB>
__global__ void __launch_bounds__(256)
tgemm(int nt, int kAo, int kBo,
      const __grid_constant__ CUtensorMap tmA,
      const __grid_constant__ CUtensorMap tmB,
      void* __restrict__ Cvp, int ldc, size_t sC,
      const float* __restrict__ bias,
      const float* __restrict__ res, size_t sR,
      float alpha)
{
    extern __shared__ char smraw[];
    const uint32_t sb = smem_u32(smraw);
    const uint32_t tb = (sb + 1023) & ~1023u;        // 1024-aligned tiles
    const uint32_t mb = tb + 3 * STAGE_B;            // 3 mbarriers

    const int bz = blockIdx.z;
    const int m0 = blockIdx.y * 128;
    const int n0 = blockIdx.x * 128;
    const int tid  = threadIdx.x;
    const int lane = tid & 31;
    const int wid  = tid >> 5;
    const int wm   = wid >> 1;
    const int wn   = wid & 1;
    const int grp  = lane >> 2;
    const int tig  = lane & 3;
    const int lrow = lane & 15;
    const int lkb  = (lane >> 4) << 4;   // 0 or 16 bytes
    const int zA = BA ? bz : 0;
    const int zB = BB ? bz : 0;

    if (RES) res += sR * bz;

    if (tid == 0) {
        #pragma unroll
        for (int s = 0; s < 3; s++) mbar_init(mb + 8 * s, 1);
    }
    __syncthreads();

    if (tid == 0) {
        #pragma unroll
        for (int s = 0; s < 3; s++) {
            mbar_expect_tx(mb + 8 * s, STAGE_B);
            tma_load3d(tb + s * STAGE_B,          &tmA, kAo + s * 64, m0, zA, mb + 8 * s);
            tma_load3d(tb + s * STAGE_B + TILE_B, &tmB, kBo + s * 64, n0, zB, mb + 8 * s);
        }
    }

    float acc[2][8][4];
    #pragma unroll
    for (int mi = 0; mi < 2; mi++)
        #pragma unroll
        for (int ni = 0; ni < 8; ni++)
            #pragma unroll
            for (int r = 0; r < 4; r++)
                acc[mi][ni][r] = 0.f;

    for (int t = 0; t < nt; t++) {
        const int st = t - (t / 3) * 3;
        mbar_wait(mb + 8 * st, (t / 3) & 1);
        const uint32_t As = tb + st * STAGE_B;
        const uint32_t Bs = As + TILE_B;

        #pragma unroll
        for (int ks = 0; ks < 4; ks++) {        // 4 k16 steps (64 elems)
            const uint32_t colb = ks * 32 + lkb;
            uint32_t af[2][4];
            #pragma unroll
            for (int mi = 0; mi < 2; mi++) {
                int row = wm * 32 + mi * 16 + lrow;
                ldsm_x4(af[mi][0], af[mi][1], af[mi][2], af[mi][3],
                        As + swz(row * 128 + colb));
            }
            uint32_t bfr[8][2];
            #pragma unroll
            for (int nb = 0; nb < 4; nb++) {
                int row = wn * 64 + nb * 16 + lrow;
                uint32_t r0, r1, r2, r3;
                ldsm_x4(r0, r1, r2, r3, Bs + swz(row * 128 + colb));
                bfr[nb * 2][0] = r0; bfr[nb * 2][1] = r2;
                bfr[nb * 2 + 1][0] = r1; bfr[nb * 2 + 1][1] = r3;
            }
            #pragma unroll
            for (int mi = 0; mi < 2; mi++)
                #pragma unroll
                for (int ni = 0; ni < 8; ni++)
                    mma_bf16(acc[mi][ni], af[mi], bfr[ni]);
        }
        __syncthreads();
        if (tid == 0 && t + 3 < nt) {
            mbar_expect_tx(mb + 8 * st, STAGE_B);
            tma_load3d(tb + st * STAGE_B,          &tmA, kAo + (t + 3) * 64, m0, zA, mb + 8 * st);
            tma_load3d(tb + st * STAGE_B + TILE_B, &tmB, kBo + (t + 3) * 64, n0, zB, mb + 8 * st);
        }
    }

    // -------------------- epilogue --------------------
    float* rows_s = (float*)smraw;
    if (BIAS_MODE == 3) {
        __syncthreads();
        if (tid < 128) rows_s[tid] = 0.f;
        __syncthreads();
    }

    #pragma unroll
    for (int mi = 0; mi < 2; mi++) {
        int lr0 = wm * 32 + mi * 16 + grp;
        int r0 = m0 + lr0;
        int r1 = r0 + 8;
        float brow0 = (BIAS_MODE == 1) ? bias[r0] : 0.f;
        float brow1 = (BIAS_MODE == 1) ? bias[r1] : 0.f;
        float sc0 = 1.f, sc1 = 1.f;
        if (BIAS_MODE == 4) {
            sc0 = bias[(size_t)bz * NPIX + r0];
            sc1 = bias[(size_t)bz * NPIX + r1];
        }
        float rsum0 = 0.f, rsum1 = 0.f;
        #pragma unroll
        for (int ni = 0; ni < 8; ni++) {
            int c = n0 + wn * 64 + ni * 8 + tig * 2;
            float v0 = acc[mi][ni][0] * alpha;
            float v1 = acc[mi][ni][1] * alpha;
            float v2 = acc[mi][ni][2] * alpha;
            float v3 = acc[mi][ni][3] * alpha;
            if (BIAS_MODE == 1) { v0 += brow0; v1 += brow0; v2 += brow1; v3 += brow1; }
            if (BIAS_MODE == 2) {
                float bc0 = bias[c], bc1 = bias[c + 1];
                v0 += bc0; v1 += bc1; v2 += bc0; v3 += bc1;
            }
            if (BIAS_MODE == 3) {
                v0 = __expf(v0); v1 = __expf(v1);
                v2 = __expf(v2); v3 = __expf(v3);
                rsum0 += v0 + v1; rsum1 += v2 + v3;
            }
            if (BIAS_MODE == 4) { v0 *= sc0; v1 *= sc0; v2 *= sc1; v3 *= sc1; }
            if (RES) {
                v0 += res[(size_t)r0 * ldc + c];
                v1 += res[(size_t)r0 * ldc + c + 1];
                v2 += res[(size_t)r1 * ldc + c];
                v3 += res[(size_t)r1 * ldc + c + 1];
            }
            if (OUT_BF) {
                bf16* Cp = (bf16*)Cvp + sC * bz;
                __nv_bfloat162 w0, w1;
                w0.x = __float2bfloat16_rn(v0); w0.y = __float2bfloat16_rn(v1);
                w1.x = __float2bfloat16_rn(v2); w1.y = __float2bfloat16_rn(v3);
                *(__nv_bfloat162*)&Cp[(size_t)r0 * ldc + c] = w0;
                *(__nv_bfloat162*)&Cp[(size_t)r1 * ldc + c] = w1;
            } else {
                float* Cp = (float*)Cvp + sC * bz;
                *(float2*)&Cp[(size_t)r0 * ldc + c] = make_float2(v0, v1);
                *(float2*)&Cp[(size_t)r1 * ldc + c] = make_float2(v2, v3);
            }
        }
        if (BIAS_MODE == 3) {
            rsum0 += __shfl_xor_sync(0xffffffffu, rsum0, 1);
            rsum0 += __shfl_xor_sync(0xffffffffu, rsum0, 2);
            rsum1 += __shfl_xor_sync(0xffffffffu, rsum1, 1);
            rsum1 += __shfl_xor_sync(0xffffffffu, rsum1, 2);
            if (tig == 0) {
                atomicAdd(&rows_s[lr0], rsum0);
                atomicAdd(&rows_s[lr0 + 8], rsum1);
            }
        }
    }
    if (BIAS_MODE == 3) {
        __syncthreads();
        if (tid < 128) {
            float* psum = (float*)bias;
            psum[((size_t)bz * NPIX + m0 + tid) * JT + blockIdx.x] = rows_s[tid];
        }
    }
}

// ---------------------------------------------------------------------------
// Launch
// ---------------------------------------------------------------------------
typedef CUresult (*EncodeFn)(CUtensorMap*, CUtensorMapDataType, cuuint32_t, void*,
                             const cuuint64_t*, const cuuint64_t*, const cuuint32_t*,
                             const cuuint32_t*, CUtensorMapInterleave, CUtensorMapSwizzle,
                             CUtensorMapL2promotion, CUtensorMapFloatOOBfill);

static void encode3d(EncodeFn fn, CUtensorMap* tm, void* ptr,
                     uint64_t d0, uint64_t d1, uint64_t d2,
                     uint64_t s1_bytes, uint64_t s2_bytes)
{
    cuuint64_t dims[3]    = {d0, d1, d2};
    cuuint64_t strides[2] = {s1_bytes, s2_bytes};
    cuuint32_t box[3]     = {64, 128, 1};
    cuuint32_t es[3]      = {1, 1, 1};
    fn(tm, CU_TENSOR_MAP_DATA_TYPE_BFLOAT16, 3, ptr, dims, strides, box, es,
       CU_TENSOR_MAP_INTERLEAVE_NONE, CU_TENSOR_MAP_SWIZZLE_128B,
       CU_TENSOR_MAP_L2_PROMOTION_L2_128B, CU_TENSOR_MAP_FLOAT_OOB_FILL_NONE);
}

extern "C" void kernel_launch(void* const* d_in, const int* in_sizes, int n_in,
                              void* d_out, int out_size)
{
    const float* x        = (const float*)d_in[0];
    const float* gn_scale = (const float*)d_in[1];
    const float* gn_bias  = (const float*)d_in[2];
    const float* wq       = (const float*)d_in[3];
    const float* bq       = (const float*)d_in[4];
    const float* wk       = (const float*)d_in[5];
    const float* bk       = (const float*)d_in[6];
    const float* wv       = (const float*)d_in[7];
    const float* bv       = (const float*)d_in[8];
    const float* wp       = (const float*)d_in[9];
    const float* bp       = (const float*)d_in[10];
    float* out            = (float*)d_out;

    static bf16 *hnT = nullptr, *qkT, *v, *probs, *oT, *rwqk, *rwv, *rwp;
    static float *stats, *bqk, *psum, *inv;
    static CUtensorMap tmHN, tmWQK, tmWV, tmWP, tmV, tmP, tmO;
    if (!hnT) {
        cudaGetSymbolAddress((void**)&hnT,  g_hn);
        cudaGetSymbolAddress((void**)&qkT,  g_qk);
        cudaGetSymbolAddress((void**)&v,    g_v);
        cudaGetSymbolAddress((void**)&probs,g_p);
        cudaGetSymbolAddress((void**)&oT,   g_o);
        cudaGetSymbolAddress((void**)&rwqk, g_wqk);
        cudaGetSymbolAddress((void**)&rwv,  g_wv);
        cudaGetSymbolAddress((void**)&rwp,  g_wp);
        cudaGetSymbolAddress((void**)&bqk,  g_bqk);
        cudaGetSymbolAddress((void**)&stats, g_stats);
        cudaGetSymbolAddress((void**)&psum, g_psum);
        cudaGetSymbolAddress((void**)&inv,  g_inv);

        void* fp = nullptr;
        cudaDriverEntryPointQueryResult qr;
        cudaGetDriverEntryPoint("cuTensorMapEncodeTiled", &fp, cudaEnableDefault, &qr);
        EncodeFn enc = (EncodeFn)fp;

        const uint64_t sCNb = (uint64_t)CH * NPIX * 2;
        const uint64_t sQKb = (uint64_t)NPIX * 2 * CH * 2;
        const uint64_t sNNb = (uint64_t)NPIX * NPIX * 2;
        encode3d(enc, &tmHN,  hnT,  CH,     NPIX, BSZ, CH * 2,       sCNb);
        encode3d(enc, &tmWQK, rwqk, CH,     1024, 1,   CH * 2,       (uint64_t)1024 * CH * 2);
        encode3d(enc, &tmWV,  rwv,  CH,     CH,   1,   CH * 2,       (uint64_t)CH * CH * 2);
        encode3d(enc, &tmWP,  rwp,  CH,     CH,   1,   CH * 2,       (uint64_t)CH * CH * 2);
        encode3d(enc, &tmV,   v,    NPIX,   CH,   BSZ, NPIX * 2,     sCNb);
        encode3d(enc, &tmP,   probs,NPIX,   NPIX, BSZ, NPIX * 2,     sNNb);
        encode3d(enc, &tmO,   oT,   CH,     NPIX, BSZ, CH * 2,       sCNb);
        encode3d(enc, &tmHN,  hnT,  CH,     NPIX, BSZ, CH * 2,       sCNb);
        // qkT tensormap: dim0 = 1024 channels (q at k-offset 0, k at 512)
        static CUtensorMap dummy;
        (void)dummy;
        encode3d(enc, &tmWQK, rwqk, CH,     1024, 1,   CH * 2,       (uint64_t)1024 * CH * 2);

        cudaFuncSetAttribute(tgemm<2, false, true,  true,  false>,
                             cudaFuncAttributeMaxDynamicSharedMemorySize, GSMEM);
        cudaFuncSetAttribute(tgemm<1, false, true,  false, true >,
                             cudaFuncAttributeMaxDynamicSharedMemorySize, GSMEM);
        cudaFuncSetAttribute(tgemm<3, false, true,  true,  true >,
                             cudaFuncAttributeMaxDynamicSharedMemorySize, GSMEM);
        cudaFuncSetAttribute(tgemm<4, false, true,  true,  true >,
                             cudaFuncAttributeMaxDynamicSharedMemorySize, GSMEM);
        cudaFuncSetAttribute(tgemm<1, true,  false, false, true >,
                             cudaFuncAttributeMaxDynamicSharedMemorySize, GSMEM);
    }
    static CUtensorMap tmQK_init;
    static bool qkmap_done = false;
    if (!qkmap_done) {
        void* fp = nullptr;
        cudaDriverEntryPointQueryResult qr;
        cudaGetDriverEntryPoint("cuTensorMapEncodeTiled", &fp, cudaEnableDefault, &qr);
        EncodeFn enc = (EncodeFn)fp;
        encode3d(enc, &tmQK_init, qkT, 2 * CH, NPIX, BSZ, 2 * CH * 2,
                 (uint64_t)NPIX * 2 * CH * 2);
        qkmap_done = true;
    }
    const CUtensorMap tmQK = tmQK_init;

    const size_t sCN = (size_t)CH * NPIX;
    const size_t sNN = (size_t)NPIX * NPIX;
    const size_t sQK = (size_t)NPIX * 2 * CH;
    const float inv_sqrt_c = 0.044194173824159216f;

    round_weights_kernel<<<4 * CH * CH / 256, 256>>>(wq, wk, wv, wp, rwqk, rwv, rwp);
    bias_concat_kernel<<<4, 256>>>(bq, bk, bqk);
    gn_stats_kernel<<<BSZ * NGRP, 256>>>(x, stats);
    gn_transpose_kernel<<<dim3(NPIX / 32, CH / 32, BSZ), 256>>>(x, stats, gn_scale, gn_bias, hnT);

    // qkT = hnT . Wqk^T + bqk   (M=4096, N=1024, K=512)
    tgemm<2, false, true, true, false><<<dim3(8, 32, BSZ), 256, GSMEM>>>(
        8, 0, 0, tmHN, tmWQK, qkT, 2 * CH, sQK, bqk, nullptr, 0, 1.f);

    // v = Wv . hnT^T + bv   (M=512, N=4096, K=512)
    tgemm<1, false, true, false, true><<<dim3(32, 4, BSZ), 256, GSMEM>>>(
        8, 0, 0, tmWV, tmHN, v, NPIX, sCN, bv, nullptr, 0, 1.f);

    // p~ = exp(alpha * q . k^T)   (M=N=4096, K=512); q = qkT[:,0:512], k = qkT[:,512:1024]
    tgemm<3, false, true, true, true><<<dim3(32, 32, BSZ), 256, GSMEM>>>(
        8, 0, 512, tmQK, tmQK, probs, NPIX, sNN, psum, nullptr, 0, inv_sqrt_c);

    rowsum_inv_kernel<<<BSZ * NPIX / 256, 256>>>(psum, inv);

    // oT = diag(inv) . p~ . v^T   (M=4096, N=512, K=4096)
    tgemm<4, false, true, true, true><<<dim3(4, 32, BSZ), 256, GSMEM>>>(
        64, 0, 0, tmP, tmV, oT, CH, sCN, inv, nullptr, 0, 1.f);

    // out = Wp . oT^T + bp + x   (M=512, N=4096, K=512)
    tgemm<1, true, false, false, true><<<dim3(32, 4, BSZ), 256, GSMEM>>>(
        8, 0, 0, tmWP, tmO, out, NPIX, sCN, bp, x, sCN, 1.f);
}

// round 14
// speedup vs baseline: 7.8809x; 1.0135x over previous
#include <cuda_runtime.h>
#include <cuda.h>
#include <cuda_bf16.h>
#include <math.h>
#include <stdint.h>

// ---------------------------------------------------------------------------
// AttentionBlock, bf16 mma.m16n8k16 + TMA, full/empty mbarrier pipeline
// (no block syncs in mainloop). B=2, C=512, N=4096, 32 groups.
// D[M,N] = alpha * A[M,K] . B[N,K]^T, bf16 in, fp32 accum.
// ---------------------------------------------------------------------------

static constexpr int BSZ  = 2;
static constexpr int CH   = 512;
static constexpr int NPIX = 4096;
static constexpr int NGRP = 32;
static constexpr int JT   = NPIX / 128;

typedef __nv_bfloat16 bf16;

__device__ bf16  g_hn[(size_t)BSZ * NPIX * CH];          // hnT [b][n][c]
__device__ bf16  g_qk[(size_t)BSZ * NPIX * 2 * CH];      // qkT [b][n][1024]
__device__ bf16  g_v [(size_t)BSZ * CH * NPIX];          // v   [b][c][n]
__device__ bf16  g_o [(size_t)BSZ * NPIX * CH];          // oT  [b][n][c]
__device__ bf16  g_p [(size_t)BSZ * NPIX * NPIX];        // p~ = exp(logit)
__device__ float g_psum[(size_t)BSZ * NPIX * JT];
__device__ float g_inv [(size_t)BSZ * NPIX];
__device__ bf16  g_wqk[2 * CH * CH];
__device__ bf16  g_wv[CH * CH];
__device__ bf16  g_wp[CH * CH];
__device__ float g_bqk[2 * CH];
__device__ float g_stats[BSZ * NGRP * 2];

// ---------------------------------------------------------------------------
__device__ __forceinline__ uint32_t smem_u32(const void* p) {
    return (uint32_t)__cvta_generic_to_shared(p);
}
__device__ __forceinline__ uint32_t swz(uint32_t off) {
    return off ^ ((off >> 3) & 0x70);
}
__device__ __forceinline__ void mbar_init(uint32_t a, uint32_t cnt) {
    asm volatile("mbarrier.init.shared.b64 [%0], %1;" :: "r"(a), "r"(cnt) : "memory");
}
__device__ __forceinline__ void mbar_arrive(uint32_t a) {
    asm volatile("mbarrier.arrive.shared.b64 _, [%0];" :: "r"(a) : "memory");
}
__device__ __forceinline__ void mbar_expect_tx(uint32_t a, uint32_t bytes) {
    asm volatile("mbarrier.arrive.expect_tx.shared.b64 _, [%0], %1;"
                 :: "r"(a), "r"(bytes) : "memory");
}
__device__ __forceinline__ void mbar_wait(uint32_t a, uint32_t parity) {
    asm volatile(
        "{\n\t.reg .pred P;\n\t"
        "W_%=:\n\t"
        "mbarrier.try_wait.parity.acquire.cta.shared::cta.b64 P, [%0], %1, 0x989680;\n\t"
        "@!P bra W_%=;\n\t}"
        :: "r"(a), "r"(parity) : "memory");
}
__device__ __forceinline__ void tma_load3d(uint32_t dst, const CUtensorMap* tm,
                                           int x, int y, int z, uint32_t mbar) {
    asm volatile(
        "cp.async.bulk.tensor.3d.shared::cta.global.tile.mbarrier::complete_tx::bytes "
        "[%0], [%1, {%2, %3, %4}], [%5];"
        :: "r"(dst), "l"(tm), "r"(x), "r"(y), "r"(z), "r"(mbar) : "memory");
}
__device__ __forceinline__ void ldsm_x4(uint32_t& r0, uint32_t& r1,
                                        uint32_t& r2, uint32_t& r3, uint32_t a) {
    asm volatile("ldmatrix.sync.aligned.m8n8.x4.shared.b16 {%0,%1,%2,%3}, [%4];"
                 : "=r"(r0), "=r"(r1), "=r"(r2), "=r"(r3) : "r"(a));
}
__device__ __forceinline__ void mma_bf16(float* c, const uint32_t* a, const uint32_t* b) {
    asm volatile(
        "mma.sync.aligned.m16n8k16.row.col.f32.bf16.bf16.f32 "
        "{%0,%1,%2,%3}, {%4,%5,%6,%7}, {%8,%9}, {%0,%1,%2,%3};"
        : "+f"(c[0]), "+f"(c[1]), "+f"(c[2]), "+f"(c[3])
        : "r"(a[0]), "r"(a[1]), "r"(a[2]), "r"(a[3]), "r"(b[0]), "r"(b[1]));
}

// ---------------------------------------------------------------------------
// prep kernels
// ---------------------------------------------------------------------------
__global__ void round_weights_kernel(const float* __restrict__ a, const float* __restrict__ b,
                                     const float* __restrict__ c, const float* __restrict__ d,
                                     bf16* __restrict__ wqk, bf16* __restrict__ wv,
                                     bf16* __restrict__ wp)
{
    int i = blockIdx.x * blockDim.x + threadIdx.x;
    int w = i >> 18;
    int off = i & ((1 << 18) - 1);
    const float* src = (w == 0) ? a : (w == 1) ? b : (w == 2) ? c : d;
    bf16* dst = (w == 0) ? wqk : (w == 1) ? (wqk + CH * CH) : (w == 2) ? wv : wp;
    dst[off] = __float2bfloat16_rn(src[off]);
}
__global__ void bias_concat_kernel(const float* __restrict__ bq,
                                   const float* __restrict__ bk,
                                   float* __restrict__ o)
{
    int i = blockIdx.x * blockDim.x + threadIdx.x;
    o[i] = (i < CH) ? bq[i] : bk[i - CH];
}

__global__ void gn_stats_kernel(const float* __restrict__ x, float* __restrict__ stats)
{
    const int NPG = (CH / NGRP) * NPIX;   // 65536 floats = 16384 float4
    const float4* xp = (const float4*)(x + (size_t)blockIdx.x * NPG);
    float s = 0.f, ss = 0.f;
    for (int i = threadIdx.x; i < NPG / 4; i += blockDim.x) {
        float4 v = xp[i];
        s  += v.x + v.y + v.z + v.w;
        ss += v.x * v.x + v.y * v.y + v.z * v.z + v.w * v.w;
    }
    __shared__ float sh[64];
    #pragma unroll
    for (int o = 16; o; o >>= 1) {
        s  += __shfl_xor_sync(0xffffffffu, s,  o);
        ss += __shfl_xor_sync(0xffffffffu, ss, o);
    }
    int wid = threadIdx.x >> 5, lid = threadIdx.x & 31;
    if (lid == 0) { sh[wid] = s; sh[32 + wid] = ss; }
    __syncthreads();
    if (threadIdx.x < 32) {
        s  = (lid < 8) ? sh[lid]      : 0.f;
        ss = (lid < 8) ? sh[32 + lid] : 0.f;
        #pragma unroll
        for (int o = 4; o; o >>= 1) {
            s  += __shfl_xor_sync(0xffffffffu, s,  o);
            ss += __shfl_xor_sync(0xffffffffu, ss, o);
        }
        if (lid == 0) {
            float mean = s / (float)NPG;
            float var  = ss / (float)NPG - mean * mean;
            stats[blockIdx.x * 2 + 0] = mean;
            stats[blockIdx.x * 2 + 1] = rsqrtf(var + 1e-6f);
        }
    }
}

// Normalize + transpose: x[b][c][n] -> hnT[b][n][c] bf16. Tile 32c x 128n.
// smem row stride 132 floats (528B, 16B-aligned, conflict-spread).
__global__ void __launch_bounds__(256)
gn_transpose_kernel(const float* __restrict__ x, const float* __restrict__ stats,
                    const float* __restrict__ scale, const float* __restrict__ bias,
                    bf16* __restrict__ hnT)
{
    __shared__ float tile[32 * 132];
    const int n0 = blockIdx.x * 128;
    const int c0 = blockIdx.y * 32;
    const int b  = blockIdx.z;
    const float* xb = x + (size_t)b * CH * NPIX;
    bf16* hb = hnT + (size_t)b * NPIX * CH;
    const int tid = threadIdx.x;

    #pragma unroll
    for (int r = 0; r < 4; r++) {
        int idx = r * 256 + tid;          // 1024 float4 slots
        int ci  = idx >> 5;               // 0..31
        int n4  = idx & 31;               // 0..31 (x4 floats)
        int c   = c0 + ci;
        int g   = c >> 4;
        float mean = stats[(b * NGRP + g) * 2 + 0];
        float rstd = stats[(b * NGRP + g) * 2 + 1];
        float sc = scale[c], bi = bias[c];
        float4 v = *(const float4*)&xb[(size_t)c * NPIX + n0 + n4 * 4];
        float* tp = &tile[ci * 132 + n4 * 4];
        tp[0] = (v.x - mean) * rstd * sc + bi;
        tp[1] = (v.y - mean) * rstd * sc + bi;
        tp[2] = (v.z - mean) * rstd * sc + bi;
        tp[3] = (v.w - mean) * rstd * sc + bi;
    }
    __syncthreads();
    #pragma unroll
    for (int r = 0; r < 2; r++) {
        int idx = r * 256 + tid;          // 512 slots: 128n x 4 c-quads
        int ni  = idx >> 2;               // 0..127
        int cq  = idx & 3;                // 0..3 -> 8 c's each
        uint32_t w[4];
        #pragma unroll
        for (int j = 0; j < 4; j++) {
            float lo = tile[(cq * 8 + 2 * j)     * 132 + ni];
            float hi = tile[(cq * 8 + 2 * j + 1) * 132 + ni];
            __nv_bfloat162 p;
            p.x = __float2bfloat16_rn(lo);
            p.y = __float2bfloat16_rn(hi);
            w[j] = *(uint32_t*)&p;
        }
        *(uint4*)&hb[(size_t)(n0 + ni) * CH + c0 + cq * 8] = *(uint4*)w;
    }
}

__global__ void rowsum_inv_kernel(const float* __restrict__ psum, float* __restrict__ inv)
{
    int i = blockIdx.x * blockDim.x + threadIdx.x;
    const float* p = psum + (size_t)i * JT;
    float s = 0.f;
    #pragma unroll
    for (int j = 0; j < JT; j++) s += p[j];
    inv[i] = 1.f / s;
}

// ---------------------------------------------------------------------------
// TMA-fed bf16 GEMM. BM=BN=128, BK=64 (SW128), 3 stages, 8 warps (4x2),
// warp tile 32x64, m16n8k16. Full/empty mbarrier pipeline, no mainloop syncs.
// BIAS_MODE: 0 none, 1 bias[m], 2 bias[n], 3 softmax epi (exp + psum),
//            4 rowscale (bias = inv[b*NPIX+m]).  BA/BB: operand batched.
// ---------------------------------------------------------------------------
static constexpr int TILE_B  = 128 * 128;            // 16KB per operand tile
static constexpr int STAGE_B = 2 * TILE_B;           // 32KB
static constexpr int GSMEM   = 1024 + 3 * STAGE_B + 128;

template <int BIAS_MODE, bool RES, bool OUT_BF, bool BA, bool BB>
__global__ void __launch_bounds__(256)
tgemm(int nt, int kAo, int kBo,
      const __grid_constant__ CUtensorMap tmA,
      const __grid_constant__ CUtensorMap tmB,
      void* __restrict__ Cvp, int ldc, size_t sC,
      const float* __restrict__ bias,
      const float* __restrict__ res, size_t sR,
      float alpha)
{
    extern __shared__ char smraw[];
    const uint32_t sb = smem_u32(smraw);
    const uint32_t tb = (sb + 1023) & ~1023u;        // 1024-aligned tiles
    const uint32_t fullb  = tb + 3 * STAGE_B;        // full[3] @ +0,8,16
    const uint32_t emptyb = fullb + 24;              // empty[3] @ +0,8,16

    const int bz = blockIdx.z;
    const int m0 = blockIdx.y * 128;
    const int n0 = blockIdx.x * 128;
    const int tid  = threadIdx.x;
    const int lane = tid & 31;
    const int wid  = tid >> 5;
    const int wm   = wid >> 1;
    const int wn   = wid & 1;
    const int grp  = lane >> 2;
    const int tig  = lane & 3;
    const int lrow = lane & 15;
    const int lkb  = (lane >> 4) << 4;
    const int zA = BA ? bz : 0;
    const int zB = BB ? bz : 0;

    if (RES) res += sR * bz;

    if (tid == 0) {
        #pragma unroll
        for (int s = 0; s < 3; s++) {
            mbar_init(fullb  + 8 * s, 1);
            mbar_init(emptyb + 8 * s, 8);
        }
    }
    __syncthreads();

    if (tid == 0) {
        #pragma unroll
        for (int s = 0; s < 3; s++) {
            mbar_expect_tx(fullb + 8 * s, STAGE_B);
            tma_load3d(tb + s * STAGE_B,          &tmA, kAo + s * 64, m0, zA, fullb + 8 * s);
            tma_load3d(tb + s * STAGE_B + TILE_B, &tmB, kBo + s * 64, n0, zB, fullb + 8 * s);
        }
    }

    float acc[2][8][4];
    #pragma unroll
    for (int mi = 0; mi < 2; mi++)
        #pragma unroll
        for (int ni = 0; ni < 8; ni++)
            #pragma unroll
            for (int r = 0; r < 4; r++)
                acc[mi][ni][r] = 0.f;

    for (int t = 0; t < nt; t++) {
        const int tp = t / 3;
        const int st = t - tp * 3;
        const uint32_t ph = tp & 1;
        mbar_wait(fullb + 8 * st, ph);
        const uint32_t As = tb + st * STAGE_B;
        const uint32_t Bs = As + TILE_B;

        #pragma unroll
        for (int ks = 0; ks < 4; ks++) {
            const uint32_t colb = ks * 32 + lkb;
            uint32_t af[2][4];
            #pragma unroll
            for (int mi = 0; mi < 2; mi++) {
                int row = wm * 32 + mi * 16 + lrow;
                ldsm_x4(af[mi][0], af[mi][1], af[mi][2], af[mi][3],
                        As + swz(row * 128 + colb));
            }
            uint32_t bfr[8][2];
            #pragma unroll
            for (int nb = 0; nb < 4; nb++) {
                int row = wn * 64 + nb * 16 + lrow;
                uint32_t r0, r1, r2, r3;
                ldsm_x4(r0, r1, r2, r3, Bs + swz(row * 128 + colb));
                bfr[nb * 2][0] = r0; bfr[nb * 2][1] = r2;
                bfr[nb * 2 + 1][0] = r1; bfr[nb * 2 + 1][1] = r3;
            }
            #pragma unroll
            for (int mi = 0; mi < 2; mi++)
                #pragma unroll
                for (int ni = 0; ni < 8; ni++)
                    mma_bf16(acc[mi][ni], af[mi], bfr[ni]);
        }
        // stage consumed (mma issue implies ldsm data landed): release it
        if (lane == 0) mbar_arrive(emptyb + 8 * st);
        if (tid == 0 && t + 3 < nt) {
            mbar_wait(emptyb + 8 * st, ph);     // all 8 warps released stage st
            mbar_expect_tx(fullb + 8 * st, STAGE_B);
            tma_load3d(tb + st * STAGE_B,          &tmA, kAo + (t + 3) * 64, m0, zA, fullb + 8 * st);
            tma_load3d(tb + st * STAGE_B + TILE_B, &tmB, kBo + (t + 3) * 64, n0, zB, fullb + 8 * st);
        }
    }

    // -------------------- epilogue --------------------
    float* rows_s = (float*)smraw;
    if (BIAS_MODE == 3) {
        __syncthreads();
        if (tid < 128) rows_s[tid] = 0.f;
        __syncthreads();
    }

    #pragma unroll
    for (int mi = 0; mi < 2; mi++) {
        int lr0 = wm * 32 + mi * 16 + grp;
        int r0 = m0 + lr0;
        int r1 = r0 + 8;
        float brow0 = (BIAS_MODE == 1) ? bias[r0] : 0.f;
        float brow1 = (BIAS_MODE == 1) ? bias[r1] : 0.f;
        float sc0 = 1.f, sc1 = 1.f;
        if (BIAS_MODE == 4) {
            sc0 = bias[(size_t)bz * NPIX + r0];
            sc1 = bias[(size_t)bz * NPIX + r1];
        }
        float rsum0 = 0.f, rsum1 = 0.f;
        #pragma unroll
        for (int ni = 0; ni < 8; ni++) {
            int c = n0 + wn * 64 + ni * 8 + tig * 2;
            float v0 = acc[mi][ni][0] * alpha;
            float v1 = acc[mi][ni][1] * alpha;
            float v2 = acc[mi][ni][2] * alpha;
            float v3 = acc[mi][ni][3] * alpha;
            if (BIAS_MODE == 1) { v0 += brow0; v1 += brow0; v2 += brow1; v3 += brow1; }
            if (BIAS_MODE == 2) {
                float bc0 = bias[c], bc1 = bias[c + 1];
                v0 += bc0; v1 += bc1; v2 += bc0; v3 += bc1;
            }
            if (BIAS_MODE == 3) {
                v0 = __expf(v0); v1 = __expf(v1);
                v2 = __expf(v2); v3 = __expf(v3);
                rsum0 += v0 + v1; rsum1 += v2 + v3;
            }
            if (BIAS_MODE == 4) { v0 *= sc0; v1 *= sc0; v2 *= sc1; v3 *= sc1; }
            if (RES) {
                v0 += res[(size_t)r0 * ldc + c];
                v1 += res[(size_t)r0 * ldc + c + 1];
                v2 += res[(size_t)r1 * ldc + c];
                v3 += res[(size_t)r1 * ldc + c + 1];
            }
            if (OUT_BF) {
                bf16* Cp = (bf16*)Cvp + sC * bz;
                __nv_bfloat162 w0, w1;
                w0.x = __float2bfloat16_rn(v0); w0.y = __float2bfloat16_rn(v1);
                w1.x = __float2bfloat16_rn(v2); w1.y = __float2bfloat16_rn(v3);
                *(__nv_bfloat162*)&Cp[(size_t)r0 * ldc + c] = w0;
                *(__nv_bfloat162*)&Cp[(size_t)r1 * ldc + c] = w1;
            } else {
                float* Cp = (float*)Cvp + sC * bz;
                *(float2*)&Cp[(size_t)r0 * ldc + c] = make_float2(v0, v1);
                *(float2*)&Cp[(size_t)r1 * ldc + c] = make_float2(v2, v3);
            }
        }
        if (BIAS_MODE == 3) {
            rsum0 += __shfl_xor_sync(0xffffffffu, rsum0, 1);
            rsum0 += __shfl_xor_sync(0xffffffffu, rsum0, 2);
            rsum1 += __shfl_xor_sync(0xffffffffu, rsum1, 1);
            rsum1 += __shfl_xor_sync(0xffffffffu, rsum1, 2);
            if (tig == 0) {
                atomicAdd(&rows_s[lr0], rsum0);
                atomicAdd(&rows_s[lr0 + 8], rsum1);
            }
        }
    }
    if (BIAS_MODE == 3) {
        __syncthreads();
        if (tid < 128) {
            float* psum = (float*)bias;
            psum[((size_t)bz * NPIX + m0 + tid) * JT + blockIdx.x] = rows_s[tid];
        }
    }
}

// ---------------------------------------------------------------------------
// Launch
// ---------------------------------------------------------------------------
typedef CUresult (*EncodeFn)(CUtensorMap*, CUtensorMapDataType, cuuint32_t, void*,
                             const cuuint64_t*, const cuuint64_t*, const cuuint32_t*,
                             const cuuint32_t*, CUtensorMapInterleave, CUtensorMapSwizzle,
                             CUtensorMapL2promotion, CUtensorMapFloatOOBfill);

static void encode3d(EncodeFn fn, CUtensorMap* tm, void* ptr,
                     uint64_t d0, uint64_t d1, uint64_t d2,
                     uint64_t s1_bytes, uint64_t s2_bytes)
{
    cuuint64_t dims[3]    = {d0, d1, d2};
    cuuint64_t strides[2] = {s1_bytes, s2_bytes};
    cuuint32_t box[3]     = {64, 128, 1};
    cuuint32_t es[3]      = {1, 1, 1};
    fn(tm, CU_TENSOR_MAP_DATA_TYPE_BFLOAT16, 3, ptr, dims, strides, box, es,
       CU_TENSOR_MAP_INTERLEAVE_NONE, CU_TENSOR_MAP_SWIZZLE_128B,
       CU_TENSOR_MAP_L2_PROMOTION_L2_128B, CU_TENSOR_MAP_FLOAT_OOB_FILL_NONE);
}

extern "C" void kernel_launch(void* const* d_in, const int* in_sizes, int n_in,
                              void* d_out, int out_size)
{
    const float* x        = (const float*)d_in[0];
    const float* gn_scale = (const float*)d_in[1];
    const float* gn_bias  = (const float*)d_in[2];
    const float* wq       = (const float*)d_in[3];
    const float* bq       = (const float*)d_in[4];
    const float* wk       = (const float*)d_in[5];
    const float* bk       = (const float*)d_in[6];
    const float* wv       = (const float*)d_in[7];
    const float* bv       = (const float*)d_in[8];
    const float* wp       = (const float*)d_in[9];
    const float* bp       = (const float*)d_in[10];
    float* out            = (float*)d_out;

    static bf16 *hnT = nullptr, *qkT, *v, *probs, *oT, *rwqk, *rwv, *rwp;
    static float *stats, *bqk, *psum, *inv;
    static CUtensorMap tmHN, tmWQK, tmWV, tmWP, tmV, tmP, tmO, tmQK;
    if (!hnT) {
        cudaGetSymbolAddress((void**)&hnT,  g_hn);
        cudaGetSymbolAddress((void**)&qkT,  g_qk);
        cudaGetSymbolAddress((void**)&v,    g_v);
        cudaGetSymbolAddress((void**)&probs,g_p);
        cudaGetSymbolAddress((void**)&oT,   g_o);
        cudaGetSymbolAddress((void**)&rwqk, g_wqk);
        cudaGetSymbolAddress((void**)&rwv,  g_wv);
        cudaGetSymbolAddress((void**)&rwp,  g_wp);
        cudaGetSymbolAddress((void**)&bqk,  g_bqk);
        cudaGetSymbolAddress((void**)&stats, g_stats);
        cudaGetSymbolAddress((void**)&psum, g_psum);
        cudaGetSymbolAddress((void**)&inv,  g_inv);

        void* fp = nullptr;
        cudaDriverEntryPointQueryResult qr;
        cudaGetDriverEntryPoint("cuTensorMapEncodeTiled", &fp, cudaEnableDefault, &qr);
        EncodeFn enc = (EncodeFn)fp;

        const uint64_t sCNb = (uint64_t)CH * NPIX * 2;
        const uint64_t sNNb = (uint64_t)NPIX * NPIX * 2;
        const uint64_t sQKb = (uint64_t)NPIX * 2 * CH * 2;
        encode3d(enc, &tmHN,  hnT,  CH,     NPIX, BSZ, CH * 2,     sCNb);
        encode3d(enc, &tmWQK, rwqk, CH,     1024, 1,   CH * 2,     (uint64_t)1024 * CH * 2);
        encode3d(enc, &tmWV,  rwv,  CH,     CH,   1,   CH * 2,     (uint64_t)CH * CH * 2);
        encode3d(enc, &tmWP,  rwp,  CH,     CH,   1,   CH * 2,     (uint64_t)CH * CH * 2);
        encode3d(enc, &tmV,   v,    NPIX,   CH,   BSZ, NPIX * 2,   sCNb);
        encode3d(enc, &tmP,   probs,NPIX,   NPIX, BSZ, NPIX * 2,   sNNb);
        encode3d(enc, &tmO,   oT,   CH,     NPIX, BSZ, CH * 2,     sCNb);
        encode3d(enc, &tmQK,  qkT,  2 * CH, NPIX, BSZ, 2 * CH * 2, sQKb);

        cudaFuncSetAttribute(tgemm<2, false, true,  true,  false>,
                             cudaFuncAttributeMaxDynamicSharedMemorySize, GSMEM);
        cudaFuncSetAttribute(tgemm<1, false, true,  false, true >,
                             cudaFuncAttributeMaxDynamicSharedMemorySize, GSMEM);
        cudaFuncSetAttribute(tgemm<3, false, true,  true,  true >,
                             cudaFuncAttributeMaxDynamicSharedMemorySize, GSMEM);
        cudaFuncSetAttribute(tgemm<4, false, true,  true,  true >,
                             cudaFuncAttributeMaxDynamicSharedMemorySize, GSMEM);
        cudaFuncSetAttribute(tgemm<1, true,  false, false, true >,
                             cudaFuncAttributeMaxDynamicSharedMemorySize, GSMEM);
    }

    const size_t sCN = (size_t)CH * NPIX;
    const size_t sNN = (size_t)NPIX * NPIX;
    const size_t sQK = (size_t)NPIX * 2 * CH;
    const float inv_sqrt_c = 0.044194173824159216f;

    round_weights_kernel<<<4 * CH * CH / 256, 256>>>(wq, wk, wv, wp, rwqk, rwv, rwp);
    bias_concat_kernel<<<4, 256>>>(bq, bk, bqk);
    gn_stats_kernel<<<BSZ * NGRP, 256>>>(x, stats);
    gn_transpose_kernel<<<dim3(NPIX / 128, CH / 32, BSZ), 256>>>(x, stats, gn_scale, gn_bias, hnT);

    // qkT = hnT . Wqk^T + bqk   (M=4096, N=1024, K=512)
    tgemm<2, false, true, true, false><<<dim3(8, 32, BSZ), 256, GSMEM>>>(
        8, 0, 0, tmHN, tmWQK, qkT, 2 * CH, sQK, bqk, nullptr, 0, 1.f);

    // v = Wv . hnT^T + bv   (M=512, N=4096, K=512)
    tgemm<1, false, true, false, true><<<dim3(32, 4, BSZ), 256, GSMEM>>>(
        8, 0, 0, tmWV, tmHN, v, NPIX, sCN, bv, nullptr, 0, 1.f);

    // p~ = exp(alpha * q . k^T)   (M=N=4096, K=512)
    tgemm<3, false, true, true, true><<<dim3(32, 32, BSZ), 256, GSMEM>>>(
        8, 0, 512, tmQK, tmQK, probs, NPIX, sNN, psum, nullptr, 0, inv_sqrt_c);

    rowsum_inv_kernel<<<BSZ * NPIX / 256, 256>>>(psum, inv);

    // oT = diag(inv) . p~ . v^T   (M=4096, N=512, K=4096)
    tgemm<4, false, true, true, true><<<dim3(4, 32, BSZ), 256, GSMEM>>>(
        64, 0, 0, tmP, tmV, oT, CH, sCN, inv, nullptr, 0, 1.f);

    // out = Wp . oT^T + bp + x   (M=512, N=4096, K=512)
    tgemm<1, true, false, false, true><<<dim3(32, 4, BSZ), 256, GSMEM>>>(
        8, 0, 0, tmWP, tmO, out, NPIX, sCN, bp, x, sCN, 1.f);
}